// round 11
// baseline (speedup 1.0000x reference)
#include <cuda_runtime.h>
#include <cuda_bf16.h>
#include <cstdint>

#define NTOK 6272
#define CDIM 1024
#define HEADS 16
#define HD 64
#define SFR 32
#define PTOK 196
#define MKV 1960
#define KT 32
#define MKPAD 1984
#define NSPL 2
#define NT_S 31
#define KVSPL (NT_S * KT)

#define KDIM 1024
#define NQKV 3072

// Scratch (no allocations anywhere)
__device__ float g_qkv[3u * HEADS * NTOK * HD];
__device__ __nv_bfloat16 g_ahi[(size_t)NTOK * KDIM];
__device__ __nv_bfloat16 g_alo[(size_t)NTOK * KDIM];
__device__ __nv_bfloat16 g_wqhi[(size_t)NQKV * KDIM];
__device__ __nv_bfloat16 g_wqlo[(size_t)NQKV * KDIM];
__device__ __nv_bfloat16 g_wphi[(size_t)1024 * KDIM];
__device__ __nv_bfloat16 g_wplo[(size_t)1024 * KDIM];
__device__ __nv_bfloat16 g_qhi[(size_t)HEADS * NTOK * HD];
__device__ __nv_bfloat16 g_qlo[(size_t)HEADS * NTOK * HD];
__device__ __nv_bfloat16 g_khi[(size_t)HEADS * NTOK * HD];
__device__ __nv_bfloat16 g_klo[(size_t)HEADS * NTOK * HD];
__device__ __nv_bfloat16 g_vhi[(size_t)HEADS * NTOK * HD];
__device__ __nv_bfloat16 g_vlo[(size_t)HEADS * NTOK * HD];
__device__ int   g_gidx2[SFR * MKPAD];
__device__ float g_bias2[SFR * MKPAD];
__device__ float g_pacc[(size_t)NSPL * SFR * HEADS * PTOK * HD];
__device__ float g_pl[NSPL * SFR * HEADS * PTOK];

// ---------------------------------------------------------------------------
// helpers
// ---------------------------------------------------------------------------
__device__ __forceinline__ uint32_t smem_u32(const void* p) {
    uint32_t a;
    asm("{ .reg .u64 t; cvta.to.shared.u64 t, %1; cvt.u32.u64 %0, t; }"
        : "=r"(a) : "l"(p));
    return a;
}
__device__ __forceinline__ void ldsm4(uint32_t addr, uint32_t& r0, uint32_t& r1,
                                      uint32_t& r2, uint32_t& r3) {
    asm volatile("ldmatrix.sync.aligned.m8n8.x4.shared.b16 {%0,%1,%2,%3}, [%4];"
                 : "=r"(r0), "=r"(r1), "=r"(r2), "=r"(r3) : "r"(addr));
}
__device__ __forceinline__ void ldsm4t(uint32_t addr, uint32_t& r0, uint32_t& r1,
                                       uint32_t& r2, uint32_t& r3) {
    asm volatile("ldmatrix.sync.aligned.m8n8.x4.trans.shared.b16 {%0,%1,%2,%3}, [%4];"
                 : "=r"(r0), "=r"(r1), "=r"(r2), "=r"(r3) : "r"(addr));
}
__device__ __forceinline__ void mma_bf16(float& d0, float& d1, float& d2, float& d3,
                                         uint32_t a0, uint32_t a1, uint32_t a2, uint32_t a3,
                                         uint32_t b0, uint32_t b1) {
    asm volatile(
        "mma.sync.aligned.m16n8k16.row.col.f32.bf16.bf16.f32 "
        "{%0,%1,%2,%3}, {%4,%5,%6,%7}, {%8,%9}, {%0,%1,%2,%3};"
        : "+f"(d0), "+f"(d1), "+f"(d2), "+f"(d3)
        : "r"(a0), "r"(a1), "r"(a2), "r"(a3), "r"(b0), "r"(b1));
}
__device__ __forceinline__ uint32_t pack_bf16(float a, float b) {
    __nv_bfloat162 t;
    t.x = __float2bfloat16_rn(a);
    t.y = __float2bfloat16_rn(b);
    return *(uint32_t*)&t;
}
__device__ __forceinline__ void cpa16(uint32_t dst, const void* src) {
    asm volatile("cp.async.cg.shared.global [%0], [%1], 16;"
                 :: "r"(dst), "l"(src) : "memory");
}
__device__ __forceinline__ void cpa_commit() {
    asm volatile("cp.async.commit_group;" ::: "memory");
}
__device__ __forceinline__ void cpa_wait1() {
    asm volatile("cp.async.wait_group 1;" ::: "memory");
}

// ---------------------------------------------------------------------------
// Split fp32 -> bf16 hi/lo planes into g_ahi/g_alo (same layout)
// ---------------------------------------------------------------------------
__global__ void __launch_bounds__(256)
split_kernel(const float* __restrict__ src, int n4)
{
    int i = blockIdx.x * blockDim.x + threadIdx.x;
    if (i >= n4) return;
    float4 a = ((const float4*)src)[i];
    __nv_bfloat16 h0 = __float2bfloat16_rn(a.x);
    __nv_bfloat16 h1 = __float2bfloat16_rn(a.y);
    __nv_bfloat16 h2 = __float2bfloat16_rn(a.z);
    __nv_bfloat16 h3 = __float2bfloat16_rn(a.w);
    __nv_bfloat16 l0 = __float2bfloat16_rn(a.x - __bfloat162float(h0));
    __nv_bfloat16 l1 = __float2bfloat16_rn(a.y - __bfloat162float(h1));
    __nv_bfloat16 l2 = __float2bfloat16_rn(a.z - __bfloat162float(h2));
    __nv_bfloat16 l3 = __float2bfloat16_rn(a.w - __bfloat162float(h3));
    __nv_bfloat162 hh0; hh0.x = h0; hh0.y = h1;
    __nv_bfloat162 hh1; hh1.x = h2; hh1.y = h3;
    __nv_bfloat162 ll0; ll0.x = l0; ll0.y = l1;
    __nv_bfloat162 ll1; ll1.x = l2; ll1.y = l3;
    ((__nv_bfloat162*)g_ahi)[i * 2]     = hh0;
    ((__nv_bfloat162*)g_ahi)[i * 2 + 1] = hh1;
    ((__nv_bfloat162*)g_alo)[i * 2]     = ll0;
    ((__nv_bfloat162*)g_alo)[i * 2 + 1] = ll1;
}

// ---------------------------------------------------------------------------
// Pad/clamp gather indices and fold the static-max shift into the bias.
// ---------------------------------------------------------------------------
__global__ void __launch_bounds__(256)
pad_kernel(const int* __restrict__ gidx, const float* __restrict__ abias)
{
    int i = blockIdx.x * blockDim.x + threadIdx.x;
    if (i >= SFR * MKPAD) return;
    int s = i / MKPAD, j = i - s * MKPAD;
    int jj = (j < MKV) ? j : 0;
    g_gidx2[i] = gidx[s * MKV + jj];
    g_bias2[i] = (j < MKV) ? (abias[s * MKV + j] - 10.f) : -1e9f;
}

// ---------------------------------------------------------------------------
// Transpose + split: W [1024][N] fp32 -> hi/lo [N][1024] bf16
// ---------------------------------------------------------------------------
template <int WHICH>
__global__ void __launch_bounds__(256)
wsplit_kernel(const float* __restrict__ W, int N)
{
    __nv_bfloat16* hi = (WHICH == 0) ? g_wqhi : g_wphi;
    __nv_bfloat16* lo = (WHICH == 0) ? g_wqlo : g_wplo;
    __shared__ float t[32][33];
    int n0 = blockIdx.x * 32, k0 = blockIdx.y * 32;
    int tx = threadIdx.x & 31, ty = threadIdx.x >> 5;
#pragma unroll
    for (int r = 0; r < 4; r++)
        t[ty + r * 8][tx] = W[(size_t)(k0 + ty + r * 8) * N + n0 + tx];
    __syncthreads();
#pragma unroll
    for (int r = 0; r < 4; r++) {
        int n = ty + r * 8;
        float a = t[tx][n];
        __nv_bfloat16 h = __float2bfloat16_rn(a);
        __nv_bfloat16 l = __float2bfloat16_rn(a - __bfloat162float(h));
        size_t o = (size_t)(n0 + n) * KDIM + k0 + tx;
        hi[o] = h;
        lo[o] = l;
    }
}

// ---------------------------------------------------------------------------
// HMMA GEMM v5: 128-thread CTA (4 warps, 2x2), warp tile 64x64 (6:1 mma:ldsm),
// 3-stage cp.async, 2 CTAs/SM, one barrier per chunk.
// ---------------------------------------------------------------------------
#define RSTR 24
#define TILE_E (128 * RSTR)
#define STAGE_E (4 * TILE_E)
#define STAGE_B (STAGE_E * 2)          // 24576 bytes
#define NSTAGE 3
#define GEMM_SMEM (NSTAGE * STAGE_B)   // 73728 bytes
#define OFF_AH 0
#define OFF_AL TILE_E
#define OFF_BH (2 * TILE_E)
#define OFF_BL (3 * TILE_E)

template <int MODE>
__global__ void __launch_bounds__(128, 2)
hmma_gemm_kernel(const float* __restrict__ bias, float* __restrict__ Cout, int Nc)
{
    extern __shared__ __nv_bfloat16 smb[];
    const uint32_t su = smem_u32(smb);

    const __nv_bfloat16* Bhi = (MODE == 0) ? g_wqhi : g_wphi;
    const __nv_bfloat16* Blo = (MODE == 0) ? g_wqlo : g_wplo;

    const int tid = threadIdx.x;
    const int wid = tid >> 5;
    const int lane = tid & 31;
    const int wm = wid & 1;            // 2 warps along M (64 rows each)
    const int wn = wid >> 1;           // 2 warps along N (64 cols each)
    const int bm = blockIdx.y * 128;
    const int bn = blockIdx.x * 128;

    const int grow = tid;              // each thread owns one row of each tile
    const __nv_bfloat16* pAhi = g_ahi + (size_t)(bm + grow) * KDIM;
    const __nv_bfloat16* pAlo = g_alo + (size_t)(bm + grow) * KDIM;
    const __nv_bfloat16* pBhi = Bhi + (size_t)(bn + grow) * KDIM;
    const __nv_bfloat16* pBlo = Blo + (size_t)(bn + grow) * KDIM;
    const uint32_t sstore = (uint32_t)(grow * RSTR) * 2;   // bytes

    const uint32_t aAddr = (uint32_t)((wm * 64 + (lane & 15)) * RSTR + (lane >> 4) * 8) * 2;
    const uint32_t bAddr = (uint32_t)((wn * 64 + (lane & 7) + ((lane >> 4) & 1) * 8) * RSTR
                                      + ((lane >> 3) & 1) * 8) * 2;

    float acc[4][8][4];
#pragma unroll
    for (int mf = 0; mf < 4; mf++)
#pragma unroll
        for (int nf = 0; nf < 8; nf++)
#pragma unroll
            for (int e = 0; e < 4; e++) acc[mf][nf][e] = 0.f;

    const int NCHUNK = KDIM / 16;      // 64

    // issue chunk c1 into stage slot: each thread loads 2x16B of its row per array
    auto issue_chunk = [&](int c1, int slot) {
        uint32_t sb = su + (uint32_t)slot * STAGE_B + sstore;
        int ko = c1 * 16;
        cpa16(sb + OFF_AH * 2,      pAhi + ko);
        cpa16(sb + OFF_AH * 2 + 16, pAhi + ko + 8);
        cpa16(sb + OFF_AL * 2,      pAlo + ko);
        cpa16(sb + OFF_AL * 2 + 16, pAlo + ko + 8);
        cpa16(sb + OFF_BH * 2,      pBhi + ko);
        cpa16(sb + OFF_BH * 2 + 16, pBhi + ko + 8);
        cpa16(sb + OFF_BL * 2,      pBlo + ko);
        cpa16(sb + OFF_BL * 2 + 16, pBlo + ko + 8);
    };

    issue_chunk(0, 0);
    cpa_commit();
    issue_chunk(1, 1);
    cpa_commit();

    for (int c = 0; c < NCHUNK; c++) {
        cpa_wait1();                   // chunk c's copy complete
        __syncthreads();               // all warps done computing chunk c-1

        if (c + 2 < NCHUNK) issue_chunk(c + 2, (c + 2) % NSTAGE);
        cpa_commit();

        const uint32_t sb = su + (uint32_t)(c % NSTAGE) * STAGE_B;
        uint32_t bh[16], bl[16];
#pragma unroll
        for (int j = 0; j < 4; j++) {
            ldsm4(sb + OFF_BH * 2 + bAddr + j * 16 * RSTR * 2,
                  bh[4 * j], bh[4 * j + 1], bh[4 * j + 2], bh[4 * j + 3]);
            ldsm4(sb + OFF_BL * 2 + bAddr + j * 16 * RSTR * 2,
                  bl[4 * j], bl[4 * j + 1], bl[4 * j + 2], bl[4 * j + 3]);
        }

#pragma unroll
        for (int mf = 0; mf < 4; mf++) {
            uint32_t a0, a1, a2, a3;
            ldsm4(sb + OFF_AH * 2 + aAddr + mf * 16 * RSTR * 2, a0, a1, a2, a3);
#pragma unroll
            for (int nf = 0; nf < 8; nf++)
                mma_bf16(acc[mf][nf][0], acc[mf][nf][1], acc[mf][nf][2], acc[mf][nf][3],
                         a0, a1, a2, a3, bh[nf * 2], bh[nf * 2 + 1]);
#pragma unroll
            for (int nf = 0; nf < 8; nf++)
                mma_bf16(acc[mf][nf][0], acc[mf][nf][1], acc[mf][nf][2], acc[mf][nf][3],
                         a0, a1, a2, a3, bl[nf * 2], bl[nf * 2 + 1]);
            ldsm4(sb + OFF_AL * 2 + aAddr + mf * 16 * RSTR * 2, a0, a1, a2, a3);
#pragma unroll
            for (int nf = 0; nf < 8; nf++)
                mma_bf16(acc[mf][nf][0], acc[mf][nf][1], acc[mf][nf][2], acc[mf][nf][3],
                         a0, a1, a2, a3, bh[nf * 2], bh[nf * 2 + 1]);
        }
        // no trailing barrier: next iteration's top barrier provides ordering
    }

#pragma unroll
    for (int mf = 0; mf < 4; mf++) {
#pragma unroll
        for (int nf = 0; nf < 8; nf++) {
            int m0 = bm + wm * 64 + mf * 16 + (lane >> 2);
            int col = bn + wn * 64 + nf * 8 + (lane & 3) * 2;
            float2 bb = *(const float2*)&bias[col];
            float2 v0, v1;
            v0.x = acc[mf][nf][0] + bb.x;
            v0.y = acc[mf][nf][1] + bb.y;
            v1.x = acc[mf][nf][2] + bb.x;
            v1.y = acc[mf][nf][3] + bb.y;
            if (MODE == 0) {
                int part = col >> 10;
                int h = (col >> 6) & (HEADS - 1);
                int d = col & 63;
                float* base = &g_qkv[(((size_t)part * HEADS + h) * NTOK) * HD + d];
                *(float2*)(base + (size_t)m0 * HD) = v0;
                *(float2*)(base + (size_t)(m0 + 8) * HD) = v1;
            } else {
                *(float2*)&Cout[(size_t)m0 * Nc + col] = v0;
                *(float2*)&Cout[(size_t)(m0 + 8) * Nc + col] = v1;
            }
        }
    }
}

// ---------------------------------------------------------------------------
// LayerNorm + bf16 hi/lo split of q, k, and passthrough split of v.
// ---------------------------------------------------------------------------
__global__ void __launch_bounds__(256)
ln2_kernel(const float* __restrict__ qg, const float* __restrict__ qb,
           const float* __restrict__ kg, const float* __restrict__ kb)
{
    const int HN = HEADS * NTOK;
    int warp = (blockIdx.x * blockDim.x + threadIdx.x) >> 5;
    int lane = threadIdx.x & 31;
    if (warp >= 3 * HN) return;

    const float* v = g_qkv + (size_t)warp * HD;
    float2 x = *(const float2*)&v[lane * 2];
    int part = warp / HN;
    int local = warp - part * HN;

    if (part < 2) {
        float s = x.x + x.y;
#pragma unroll
        for (int o = 16; o; o >>= 1) s += __shfl_xor_sync(0xffffffffu, s, o);
        float mu = s * (1.f / 64.f);
        float dx = x.x - mu, dy = x.y - mu;
        float ss = dx * dx + dy * dy;
#pragma unroll
        for (int o = 16; o; o >>= 1) ss += __shfl_xor_sync(0xffffffffu, ss, o);
        float rstd = rsqrtf(ss * (1.f / 64.f) + 1e-6f);
        const float* g = (part == 0) ? qg : kg;
        const float* b = (part == 0) ? qb : kb;
        x.x = dx * rstd * g[lane * 2] + b[lane * 2];
        x.y = dy * rstd * g[lane * 2 + 1] + b[lane * 2 + 1];
    }

    __nv_bfloat16* hi = (part == 0) ? g_qhi : (part == 1) ? g_khi : g_vhi;
    __nv_bfloat16* lo = (part == 0) ? g_qlo : (part == 1) ? g_klo : g_vlo;
    __nv_bfloat16 h0 = __float2bfloat16_rn(x.x);
    __nv_bfloat16 h1 = __float2bfloat16_rn(x.y);
    __nv_bfloat16 l0 = __float2bfloat16_rn(x.x - __bfloat162float(h0));
    __nv_bfloat16 l1 = __float2bfloat16_rn(x.y - __bfloat162float(h1));
    __nv_bfloat162 ph; ph.x = h0; ph.y = h1;
    __nv_bfloat162 pl; pl.x = l0; pl.y = l1;
    *(__nv_bfloat162*)&hi[(size_t)local * HD + lane * 2] = ph;
    *(__nv_bfloat162*)&lo[(size_t)local * HD + lane * 2] = pl;
}

// ---------------------------------------------------------------------------
// HMMA flash attention, KV-split x2 (R10 WIN version, unchanged).
// ---------------------------------------------------------------------------
#define AST 72
#define QLO_ELEMS (224 * AST)
#define KARR (KT * AST)
#define TILE_OFF QLO_ELEMS
#define BIAS_OFF (QLO_ELEMS + 4 * KARR)
#define AT_SMEM_BYTES (BIAS_OFF * 2 + KT * 4 + 16)

__global__ void __launch_bounds__(224, 1)
attn7_kernel()
{
    extern __shared__ __nv_bfloat16 smb2[];
    __nv_bfloat16* Qlo = smb2;
    __nv_bfloat16* Tile = smb2 + TILE_OFF;
    float* Bs = (float*)(smb2 + BIAS_OFF);
    const uint32_t su = smem_u32(smb2);

    const int s = blockIdx.x, h = blockIdx.y, split = blockIdx.z;
    const int tid = threadIdx.x, wid = tid >> 5, lane = tid & 31;
    const int m0 = wid * 32;

    const __nv_bfloat16* qh  = g_qhi + ((size_t)h * NTOK + (size_t)s * PTOK) * HD;
    const __nv_bfloat16* qlg = g_qlo + ((size_t)h * NTOK + (size_t)s * PTOK) * HD;
    const __nv_bfloat16* kh = g_khi + (size_t)h * NTOK * HD;
    const __nv_bfloat16* kl = g_klo + (size_t)h * NTOK * HD;
    const __nv_bfloat16* vh = g_vhi + (size_t)h * NTOK * HD;
    const __nv_bfloat16* vl = g_vlo + (size_t)h * NTOK * HD;

    {
        int row = tid;
        int srcr = row < PTOK ? row : PTOK - 1;
        const uint4* p = (const uint4*)(qlg + (size_t)srcr * HD);
#pragma unroll
        for (int j = 0; j < 8; j++)
            *(uint4*)&Qlo[row * AST + j * 8] = p[j];
    }

    uint32_t qf[2][4][4];
    {
        int r = lane >> 2, c2 = (lane & 3) * 2;
#pragma unroll
        for (int mf = 0; mf < 2; mf++) {
            int r0 = m0 + mf * 16 + r;
            int r1 = r0 + 8;
            if (r0 > PTOK - 1) r0 = PTOK - 1;
            if (r1 > PTOK - 1) r1 = PTOK - 1;
#pragma unroll
            for (int kf = 0; kf < 4; kf++) {
                int c0 = kf * 16 + c2;
                qf[mf][kf][0] = *(const uint32_t*)(qh + (size_t)r0 * HD + c0);
                qf[mf][kf][1] = *(const uint32_t*)(qh + (size_t)r1 * HD + c0);
                qf[mf][kf][2] = *(const uint32_t*)(qh + (size_t)r0 * HD + c0 + 8);
                qf[mf][kf][3] = *(const uint32_t*)(qh + (size_t)r1 * HD + c0 + 8);
            }
        }
    }

    float o[2][8][4];
    float lsum[2][2];
#pragma unroll
    for (int mf = 0; mf < 2; mf++) {
        lsum[mf][0] = 0.f; lsum[mf][1] = 0.f;
#pragma unroll
        for (int nf = 0; nf < 8; nf++)
#pragma unroll
            for (int e = 0; e < 4; e++) o[mf][nf][e] = 0.f;
    }

    const int pbase = s * MKPAD + split * KVSPL;

    const uint32_t kaddr = su + 2 * (TILE_OFF
        + ((lane & 7) + ((lane >> 4) & 1) * 8) * AST + ((lane >> 3) & 1) * 8);
    const uint32_t vaddr = su + 2 * (TILE_OFF + 2 * KARR
        + ((lane & 7) + ((lane >> 3) & 1) * 8) * AST + ((lane >> 4) & 1) * 8);
    const uint32_t qladdr = su + 2 * ((m0 + (lane & 15)) * AST + (lane >> 4) * 8);

    uint4 pf[5];
    float pbias = 0.f;
#pragma unroll
    for (int it = 0; it < 5; it++) {
        int slot = tid + it * 224;
        if (slot < 1024) {
            int a = slot >> 8, r = (slot >> 3) & 31, seg = slot & 7;
            int tok = g_gidx2[pbase + r];
            const __nv_bfloat16* bp = (a == 0) ? kh : (a == 1) ? kl : (a == 2) ? vh : vl;
            pf[it] = *(const uint4*)(bp + (size_t)tok * HD + seg * 8);
        }
    }
    if (tid < KT) pbias = g_bias2[pbase + tid];

    for (int t = 0; t < NT_S; t++) {
        __syncthreads();
#pragma unroll
        for (int it = 0; it < 5; it++) {
            int slot = tid + it * 224;
            if (slot < 1024) {
                int a = slot >> 8, r = (slot >> 3) & 31, seg = slot & 7;
                *(uint4*)&Tile[a * KARR + r * AST + seg * 8] = pf[it];
            }
        }
        if (tid < KT) Bs[tid] = pbias;
        __syncthreads();

        if (t + 1 < NT_S) {
            int ib = pbase + (t + 1) * KT;
#pragma unroll
            for (int it = 0; it < 5; it++) {
                int slot = tid + it * 224;
                if (slot < 1024) {
                    int a = slot >> 8, r = (slot >> 3) & 31, seg = slot & 7;
                    int tok = g_gidx2[ib + r];
                    const __nv_bfloat16* bp = (a == 0) ? kh : (a == 1) ? kl
                                             : (a == 2) ? vh : vl;
                    pf[it] = *(const uint4*)(bp + (size_t)tok * HD + seg * 8);
                }
            }
            if (tid < KT) pbias = g_bias2[ib + tid];
        }

        float sc[2][4][4];
#pragma unroll
        for (int mf = 0; mf < 2; mf++)
#pragma unroll
            for (int nf = 0; nf < 4; nf++)
#pragma unroll
                for (int e = 0; e < 4; e++) sc[mf][nf][e] = 0.f;

#pragma unroll
        for (int kf = 0; kf < 4; kf++) {
            uint32_t bh0[4], bh1[4], bl0[4], bl1[4];
            ldsm4(kaddr + kf * 32, bh0[0], bh0[1], bh0[2], bh0[3]);
            ldsm4(kaddr + kf * 32 + 16 * AST * 2, bh1[0], bh1[1], bh1[2], bh1[3]);
            ldsm4(kaddr + KARR * 2 + kf * 32, bl0[0], bl0[1], bl0[2], bl0[3]);
            ldsm4(kaddr + KARR * 2 + kf * 32 + 16 * AST * 2, bl1[0], bl1[1], bl1[2], bl1[3]);
#pragma unroll
            for (int mf = 0; mf < 2; mf++) {
                uint32_t q0 = qf[mf][kf][0], q1 = qf[mf][kf][1];
                uint32_t q2 = qf[mf][kf][2], q3 = qf[mf][kf][3];
                mma_bf16(sc[mf][0][0], sc[mf][0][1], sc[mf][0][2], sc[mf][0][3],
                         q0, q1, q2, q3, bh0[0], bh0[1]);
                mma_bf16(sc[mf][1][0], sc[mf][1][1], sc[mf][1][2], sc[mf][1][3],
                         q0, q1, q2, q3, bh0[2], bh0[3]);
                mma_bf16(sc[mf][2][0], sc[mf][2][1], sc[mf][2][2], sc[mf][2][3],
                         q0, q1, q2, q3, bh1[0], bh1[1]);
                mma_bf16(sc[mf][3][0], sc[mf][3][1], sc[mf][3][2], sc[mf][3][3],
                         q0, q1, q2, q3, bh1[2], bh1[3]);
                mma_bf16(sc[mf][0][0], sc[mf][0][1], sc[mf][0][2], sc[mf][0][3],
                         q0, q1, q2, q3, bl0[0], bl0[1]);
                mma_bf16(sc[mf][1][0], sc[mf][1][1], sc[mf][1][2], sc[mf][1][3],
                         q0, q1, q2, q3, bl0[2], bl0[3]);
                mma_bf16(sc[mf][2][0], sc[mf][2][1], sc[mf][2][2], sc[mf][2][3],
                         q0, q1, q2, q3, bl1[0], bl1[1]);
                mma_bf16(sc[mf][3][0], sc[mf][3][1], sc[mf][3][2], sc[mf][3][3],
                         q0, q1, q2, q3, bl1[2], bl1[3]);
                uint32_t ql0, ql1, ql2, ql3;
                ldsm4(qladdr + mf * 16 * AST * 2 + kf * 32, ql0, ql1, ql2, ql3);
                mma_bf16(sc[mf][0][0], sc[mf][0][1], sc[mf][0][2], sc[mf][0][3],
                         ql0, ql1, ql2, ql3, bh0[0], bh0[1]);
                mma_bf16(sc[mf][1][0], sc[mf][1][1], sc[mf][1][2], sc[mf][1][3],
                         ql0, ql1, ql2, ql3, bh0[2], bh0[3]);
                mma_bf16(sc[mf][2][0], sc[mf][2][1], sc[mf][2][2], sc[mf][2][3],
                         ql0, ql1, ql2, ql3, bh1[0], bh1[1]);
                mma_bf16(sc[mf][3][0], sc[mf][3][1], sc[mf][3][2], sc[mf][3][3],
                         ql0, ql1, ql2, ql3, bh1[2], bh1[3]);
            }
        }

        uint32_t phi[2][2][4], plo[2][2][4];
#pragma unroll
        for (int mf = 0; mf < 2; mf++) {
#pragma unroll
            for (int nf = 0; nf < 4; nf++) {
                float2 bb = *(const float2*)&Bs[nf * 8 + (lane & 3) * 2];
                float p0 = __expf(fmaf(sc[mf][nf][0], 0.125f, bb.x));
                float p1 = __expf(fmaf(sc[mf][nf][1], 0.125f, bb.y));
                float p2 = __expf(fmaf(sc[mf][nf][2], 0.125f, bb.x));
                float p3 = __expf(fmaf(sc[mf][nf][3], 0.125f, bb.y));
                lsum[mf][0] += p0 + p1;
                lsum[mf][1] += p2 + p3;
                uint32_t h01 = pack_bf16(p0, p1);
                uint32_t h23 = pack_bf16(p2, p3);
                __nv_bfloat162 hv01 = *(__nv_bfloat162*)&h01;
                __nv_bfloat162 hv23 = *(__nv_bfloat162*)&h23;
                uint32_t l01 = pack_bf16(p0 - __bfloat162float(hv01.x),
                                         p1 - __bfloat162float(hv01.y));
                uint32_t l23 = pack_bf16(p2 - __bfloat162float(hv23.x),
                                         p3 - __bfloat162float(hv23.y));
                int kf2 = nf >> 1, hf = (nf & 1) * 2;
                phi[mf][kf2][hf] = h01; phi[mf][kf2][hf + 1] = h23;
                plo[mf][kf2][hf] = l01; plo[mf][kf2][hf + 1] = l23;
            }
        }

#pragma unroll
        for (int kf = 0; kf < 2; kf++) {
            uint32_t vhf[16], vlf[16];
#pragma unroll
            for (int db = 0; db < 4; db++) {
                ldsm4t(vaddr + kf * (16 * AST * 2) + db * 32,
                       vhf[db * 4], vhf[db * 4 + 1], vhf[db * 4 + 2], vhf[db * 4 + 3]);
                ldsm4t(vaddr + KARR * 2 + kf * (16 * AST * 2) + db * 32,
                       vlf[db * 4], vlf[db * 4 + 1], vlf[db * 4 + 2], vlf[db * 4 + 3]);
            }
#pragma unroll
            for (int mf = 0; mf < 2; mf++) {
#pragma unroll
                for (int nfd = 0; nfd < 8; nfd++) {
                    int vi = (nfd >> 1) * 4 + (nfd & 1) * 2;
                    mma_bf16(o[mf][nfd][0], o[mf][nfd][1], o[mf][nfd][2], o[mf][nfd][3],
                             phi[mf][kf][0], phi[mf][kf][1], phi[mf][kf][2], phi[mf][kf][3],
                             vhf[vi], vhf[vi + 1]);
                    mma_bf16(o[mf][nfd][0], o[mf][nfd][1], o[mf][nfd][2], o[mf][nfd][3],
                             phi[mf][kf][0], phi[mf][kf][1], phi[mf][kf][2], phi[mf][kf][3],
                             vlf[vi], vlf[vi + 1]);
                    mma_bf16(o[mf][nfd][0], o[mf][nfd][1], o[mf][nfd][2], o[mf][nfd][3],
                             plo[mf][kf][0], plo[mf][kf][1], plo[mf][kf][2], plo[mf][kf][3],
                             vhf[vi], vhf[vi + 1]);
                }
            }
        }
    }

#pragma unroll
    for (int mf = 0; mf < 2; mf++) {
#pragma unroll
        for (int j = 0; j < 2; j++) {
            float v = lsum[mf][j];
            v += __shfl_xor_sync(0xffffffffu, v, 1);
            v += __shfl_xor_sync(0xffffffffu, v, 2);
            lsum[mf][j] = v;
        }
    }

    {
        int r = lane >> 2, c2 = (lane & 3) * 2;
        const size_t rrbase = ((size_t)(split * SFR + s) * HEADS + h) * PTOK;
#pragma unroll
        for (int mf = 0; mf < 2; mf++) {
            int rowq0 = m0 + mf * 16 + r;
            int rowq1 = rowq0 + 8;
            if (rowq0 < PTOK) {
                float* dst = g_pacc + (rrbase + rowq0) * HD + c2;
#pragma unroll
                for (int nfd = 0; nfd < 8; nfd++) {
                    float2 v; v.x = o[mf][nfd][0]; v.y = o[mf][nfd][1];
                    *(float2*)(dst + nfd * 8) = v;
                }
                if ((lane & 3) == 0) g_pl[rrbase + rowq0] = lsum[mf][0];
            }
            if (rowq1 < PTOK) {
                float* dst = g_pacc + (rrbase + rowq1) * HD + c2;
#pragma unroll
                for (int nfd = 0; nfd < 8; nfd++) {
                    float2 v; v.x = o[mf][nfd][2]; v.y = o[mf][nfd][3];
                    *(float2*)(dst + nfd * 8) = v;
                }
                if ((lane & 3) == 0) g_pl[rrbase + rowq1] = lsum[mf][1];
            }
        }
    }
}

// ---------------------------------------------------------------------------
// Combine split partials: (n0+n1)/(l0+l1) -> bf16 hi/lo token-major planes.
// ---------------------------------------------------------------------------
__global__ void __launch_bounds__(256)
combine_kernel()
{
    int idx = blockIdx.x * blockDim.x + threadIdx.x;
    const int total = SFR * HEADS * PTOK * (HD / 4);
    if (idx >= total) return;
    int c4 = idx & 15;
    int shp = idx >> 4;
    size_t row0 = shp;
    size_t row1 = (size_t)SFR * HEADS * PTOK + shp;
    float4 a = ((const float4*)(g_pacc + row0 * HD))[c4];
    float4 b = ((const float4*)(g_pacc + row1 * HD))[c4];
    float inv = 1.f / (g_pl[row0] + g_pl[row1]);
    float f0 = (a.x + b.x) * inv;
    float f1 = (a.y + b.y) * inv;
    float f2 = (a.z + b.z) * inv;
    float f3 = (a.w + b.w) * inv;
    int p = shp % PTOK;
    int sh = shp / PTOK;
    int hh = sh % HEADS;
    int ss = sh / HEADS;
    size_t base = (size_t)(ss * PTOK + p) * CDIM + hh * HD + c4 * 4;
    uint32_t h01 = pack_bf16(f0, f1);
    uint32_t h23 = pack_bf16(f2, f3);
    __nv_bfloat162 hv01 = *(__nv_bfloat162*)&h01;
    __nv_bfloat162 hv23 = *(__nv_bfloat162*)&h23;
    uint32_t l01 = pack_bf16(f0 - __bfloat162float(hv01.x),
                             f1 - __bfloat162float(hv01.y));
    uint32_t l23 = pack_bf16(f2 - __bfloat162float(hv23.x),
                             f3 - __bfloat162float(hv23.y));
    *(uint32_t*)&g_ahi[base] = h01;
    *(uint32_t*)&g_ahi[base + 2] = h23;
    *(uint32_t*)&g_alo[base] = l01;
    *(uint32_t*)&g_alo[base + 2] = l23;
}

// ---------------------------------------------------------------------------
extern "C" void kernel_launch(void* const* d_in, const int* in_sizes, int n_in,
                              void* d_out, int out_size)
{
    const float* x     = (const float*)d_in[0];
    const float* Wqkv  = (const float*)d_in[1];
    const float* bqkv  = (const float*)d_in[2];
    const float* qg    = (const float*)d_in[3];
    const float* qb    = (const float*)d_in[4];
    const float* kg    = (const float*)d_in[5];
    const float* kb    = (const float*)d_in[6];
    const float* Wproj = (const float*)d_in[7];
    const float* bproj = (const float*)d_in[8];
    const int*   gidx  = (const int*)d_in[9];
    const float* abias = (const float*)d_in[10];
    float* out = (float*)d_out;

    static int attr_set = 0;
    if (!attr_set) {
        cudaFuncSetAttribute(hmma_gemm_kernel<0>,
                             cudaFuncAttributeMaxDynamicSharedMemorySize, GEMM_SMEM);
        cudaFuncSetAttribute(hmma_gemm_kernel<1>,
                             cudaFuncAttributeMaxDynamicSharedMemorySize, GEMM_SMEM);
        cudaFuncSetAttribute(attn7_kernel,
                             cudaFuncAttributeMaxDynamicSharedMemorySize, AT_SMEM_BYTES);
        attr_set = 1;
    }

    const int n4 = NTOK * KDIM / 4;

    // 0) prep
    split_kernel<<<n4 / 256, 256>>>(x, n4);
    pad_kernel<<<(SFR * MKPAD + 255) / 256, 256>>>(gidx, abias);
    wsplit_kernel<0><<<dim3(NQKV / 32, KDIM / 32), 256>>>(Wqkv, NQKV);
    wsplit_kernel<1><<<dim3(1024 / 32, KDIM / 32), 256>>>(Wproj, 1024);

    // 1) QKV GEMM -> g_qkv fp32 (128-thread CTAs)
    hmma_gemm_kernel<0><<<dim3(NQKV / 128, NTOK / 128), 128, GEMM_SMEM>>>(
        bqkv, nullptr, NQKV);

    // 2) LayerNorm + bf16 hi/lo split of q/k/v
    {
        int nvec = 3 * HEADS * NTOK;
        ln2_kernel<<<(nvec * 32 + 255) / 256, 256>>>(qg, qb, kg, kb);
    }

    // 3) HMMA flash attention, KV-split x2 -> fp32 partials
    attn7_kernel<<<dim3(SFR, HEADS, NSPL), 224, AT_SMEM_BYTES>>>();

    // 3b) combine partials -> g_ahi/g_alo
    {
        const int total = SFR * HEADS * PTOK * (HD / 4);
        combine_kernel<<<(total + 255) / 256, 256>>>();
    }

    // 4) proj GEMM -> d_out (128-thread CTAs)
    hmma_gemm_kernel<1><<<dim3(1024 / 128, NTOK / 128), 128, GEMM_SMEM>>>(
        bproj, out, 1024);
}

// round 12
// speedup vs baseline: 1.0544x; 1.0544x over previous
#include <cuda_runtime.h>
#include <cuda_bf16.h>
#include <cstdint>

#define NTOK 6272
#define CDIM 1024
#define HEADS 16
#define HD 64
#define SFR 32
#define PTOK 196
#define MKV 1960
#define KT 32
#define MKPAD 1984
#define NSPL 2
#define NT_S 31
#define KVSPL (NT_S * KT)

#define KDIM 1024
#define NQKV 3072

// Scratch (no allocations anywhere)
__device__ float g_qkv[3u * HEADS * NTOK * HD];
__device__ __nv_bfloat16 g_ahi[(size_t)NTOK * KDIM];
__device__ __nv_bfloat16 g_alo[(size_t)NTOK * KDIM];
__device__ __nv_bfloat16 g_wqhi[(size_t)NQKV * KDIM];
__device__ __nv_bfloat16 g_wqlo[(size_t)NQKV * KDIM];
__device__ __nv_bfloat16 g_wphi[(size_t)1024 * KDIM];
__device__ __nv_bfloat16 g_wplo[(size_t)1024 * KDIM];
__device__ __nv_bfloat16 g_qhi[(size_t)HEADS * NTOK * HD];
__device__ __nv_bfloat16 g_qlo[(size_t)HEADS * NTOK * HD];
__device__ __nv_bfloat16 g_khi[(size_t)HEADS * NTOK * HD];
__device__ __nv_bfloat16 g_klo[(size_t)HEADS * NTOK * HD];
__device__ __nv_bfloat16 g_vhi[(size_t)HEADS * NTOK * HD];
__device__ __nv_bfloat16 g_vlo[(size_t)HEADS * NTOK * HD];
__device__ int   g_gidx2[SFR * MKPAD];
__device__ float g_bias2[SFR * MKPAD];
__device__ float g_pacc[(size_t)NSPL * SFR * HEADS * PTOK * HD];
__device__ float g_pl[NSPL * SFR * HEADS * PTOK];

// ---------------------------------------------------------------------------
// helpers
// ---------------------------------------------------------------------------
__device__ __forceinline__ uint32_t smem_u32(const void* p) {
    uint32_t a;
    asm("{ .reg .u64 t; cvta.to.shared.u64 t, %1; cvt.u32.u64 %0, t; }"
        : "=r"(a) : "l"(p));
    return a;
}
__device__ __forceinline__ void ldsm4(uint32_t addr, uint32_t& r0, uint32_t& r1,
                                      uint32_t& r2, uint32_t& r3) {
    asm volatile("ldmatrix.sync.aligned.m8n8.x4.shared.b16 {%0,%1,%2,%3}, [%4];"
                 : "=r"(r0), "=r"(r1), "=r"(r2), "=r"(r3) : "r"(addr));
}
__device__ __forceinline__ void ldsm4t(uint32_t addr, uint32_t& r0, uint32_t& r1,
                                       uint32_t& r2, uint32_t& r3) {
    asm volatile("ldmatrix.sync.aligned.m8n8.x4.trans.shared.b16 {%0,%1,%2,%3}, [%4];"
                 : "=r"(r0), "=r"(r1), "=r"(r2), "=r"(r3) : "r"(addr));
}
__device__ __forceinline__ void mma_bf16(float& d0, float& d1, float& d2, float& d3,
                                         uint32_t a0, uint32_t a1, uint32_t a2, uint32_t a3,
                                         uint32_t b0, uint32_t b1) {
    asm volatile(
        "mma.sync.aligned.m16n8k16.row.col.f32.bf16.bf16.f32 "
        "{%0,%1,%2,%3}, {%4,%5,%6,%7}, {%8,%9}, {%0,%1,%2,%3};"
        : "+f"(d0), "+f"(d1), "+f"(d2), "+f"(d3)
        : "r"(a0), "r"(a1), "r"(a2), "r"(a3), "r"(b0), "r"(b1));
}
__device__ __forceinline__ uint32_t pack_bf16(float a, float b) {
    __nv_bfloat162 t;
    t.x = __float2bfloat16_rn(a);
    t.y = __float2bfloat16_rn(b);
    return *(uint32_t*)&t;
}
__device__ __forceinline__ void cpa16(uint32_t dst, const void* src) {
    asm volatile("cp.async.cg.shared.global [%0], [%1], 16;"
                 :: "r"(dst), "l"(src) : "memory");
}
__device__ __forceinline__ void cpa_commit() {
    asm volatile("cp.async.commit_group;" ::: "memory");
}
__device__ __forceinline__ void cpa_wait1() {
    asm volatile("cp.async.wait_group 1;" ::: "memory");
}
__device__ __forceinline__ void cpa_wait0() {
    asm volatile("cp.async.wait_group 0;" ::: "memory");
}

// ---------------------------------------------------------------------------
// Split fp32 -> bf16 hi/lo planes into g_ahi/g_alo (same layout)
// ---------------------------------------------------------------------------
__global__ void __launch_bounds__(256)
split_kernel(const float* __restrict__ src, int n4)
{
    int i = blockIdx.x * blockDim.x + threadIdx.x;
    if (i >= n4) return;
    float4 a = ((const float4*)src)[i];
    __nv_bfloat16 h0 = __float2bfloat16_rn(a.x);
    __nv_bfloat16 h1 = __float2bfloat16_rn(a.y);
    __nv_bfloat16 h2 = __float2bfloat16_rn(a.z);
    __nv_bfloat16 h3 = __float2bfloat16_rn(a.w);
    __nv_bfloat16 l0 = __float2bfloat16_rn(a.x - __bfloat162float(h0));
    __nv_bfloat16 l1 = __float2bfloat16_rn(a.y - __bfloat162float(h1));
    __nv_bfloat16 l2 = __float2bfloat16_rn(a.z - __bfloat162float(h2));
    __nv_bfloat16 l3 = __float2bfloat16_rn(a.w - __bfloat162float(h3));
    __nv_bfloat162 hh0; hh0.x = h0; hh0.y = h1;
    __nv_bfloat162 hh1; hh1.x = h2; hh1.y = h3;
    __nv_bfloat162 ll0; ll0.x = l0; ll0.y = l1;
    __nv_bfloat162 ll1; ll1.x = l2; ll1.y = l3;
    ((__nv_bfloat162*)g_ahi)[i * 2]     = hh0;
    ((__nv_bfloat162*)g_ahi)[i * 2 + 1] = hh1;
    ((__nv_bfloat162*)g_alo)[i * 2]     = ll0;
    ((__nv_bfloat162*)g_alo)[i * 2 + 1] = ll1;
}

// ---------------------------------------------------------------------------
// Pad/clamp gather indices and fold the static-max shift into the bias.
// ---------------------------------------------------------------------------
__global__ void __launch_bounds__(256)
pad_kernel(const int* __restrict__ gidx, const float* __restrict__ abias)
{
    int i = blockIdx.x * blockDim.x + threadIdx.x;
    if (i >= SFR * MKPAD) return;
    int s = i / MKPAD, j = i - s * MKPAD;
    int jj = (j < MKV) ? j : 0;
    g_gidx2[i] = gidx[s * MKV + jj];
    g_bias2[i] = (j < MKV) ? (abias[s * MKV + j] - 10.f) : -1e9f;
}

// ---------------------------------------------------------------------------
// Transpose + split: W [1024][N] fp32 -> hi/lo [N][1024] bf16
// ---------------------------------------------------------------------------
template <int WHICH>
__global__ void __launch_bounds__(256)
wsplit_kernel(const float* __restrict__ W, int N)
{
    __nv_bfloat16* hi = (WHICH == 0) ? g_wqhi : g_wphi;
    __nv_bfloat16* lo = (WHICH == 0) ? g_wqlo : g_wplo;
    __shared__ float t[32][33];
    int n0 = blockIdx.x * 32, k0 = blockIdx.y * 32;
    int tx = threadIdx.x & 31, ty = threadIdx.x >> 5;
#pragma unroll
    for (int r = 0; r < 4; r++)
        t[ty + r * 8][tx] = W[(size_t)(k0 + ty + r * 8) * N + n0 + tx];
    __syncthreads();
#pragma unroll
    for (int r = 0; r < 4; r++) {
        int n = ty + r * 8;
        float a = t[tx][n];
        __nv_bfloat16 h = __float2bfloat16_rn(a);
        __nv_bfloat16 l = __float2bfloat16_rn(a - __bfloat162float(h));
        size_t o = (size_t)(n0 + n) * KDIM + k0 + tx;
        hi[o] = h;
        lo[o] = l;
    }
}

// ---------------------------------------------------------------------------
// HMMA GEMM (R7-exact WIN config): cp.async 3-stage, 2 CTAs/SM, k-chunk 16.
// ---------------------------------------------------------------------------
#define RSTR 24
#define TILE_E (128 * RSTR)
#define STAGE_E (4 * TILE_E)
#define STAGE_B (STAGE_E * 2)          // 24576 bytes
#define NSTAGE 3
#define GEMM_SMEM (NSTAGE * STAGE_B)   // 73728 bytes
#define OFF_AH 0
#define OFF_AL TILE_E
#define OFF_BH (2 * TILE_E)
#define OFF_BL (3 * TILE_E)

template <int MODE>
__global__ void __launch_bounds__(256, 2)
hmma_gemm_kernel(const float* __restrict__ bias, float* __restrict__ Cout, int Nc)
{
    extern __shared__ __nv_bfloat16 smb[];
    const uint32_t su = smem_u32(smb);

    const __nv_bfloat16* Bhi = (MODE == 0) ? g_wqhi : g_wphi;
    const __nv_bfloat16* Blo = (MODE == 0) ? g_wqlo : g_wplo;

    const int tid = threadIdx.x;
    const int wid = tid >> 5;
    const int lane = tid & 31;
    const int wm = wid & 1;
    const int wn = wid >> 1;
    const int bm = blockIdx.y * 128;
    const int bn = blockIdx.x * 128;

    const int grow = tid >> 1;
    const int ghalf = tid & 1;
    const __nv_bfloat16* pAhi = g_ahi + (size_t)(bm + grow) * KDIM + ghalf * 8;
    const __nv_bfloat16* pAlo = g_alo + (size_t)(bm + grow) * KDIM + ghalf * 8;
    const __nv_bfloat16* pBhi = Bhi + (size_t)(bn + grow) * KDIM + ghalf * 8;
    const __nv_bfloat16* pBlo = Blo + (size_t)(bn + grow) * KDIM + ghalf * 8;
    const uint32_t sstore = (uint32_t)(grow * RSTR + ghalf * 8) * 2;

    const uint32_t aAddr = (uint32_t)((wm * 64 + (lane & 15)) * RSTR + (lane >> 4) * 8) * 2;
    const uint32_t bAddr = (uint32_t)((wn * 32 + (lane & 7) + ((lane >> 4) & 1) * 8) * RSTR
                                      + ((lane >> 3) & 1) * 8) * 2;

    float acc[4][4][4];
#pragma unroll
    for (int mf = 0; mf < 4; mf++)
#pragma unroll
        for (int nf = 0; nf < 4; nf++)
#pragma unroll
            for (int e = 0; e < 4; e++) acc[mf][nf][e] = 0.f;

    const int NCHUNK = KDIM / 16;      // 64

#pragma unroll
    for (int c = 0; c < 2; c++) {
        uint32_t sb = su + (uint32_t)c * STAGE_B + sstore;
        int ko = c * 16;
        cpa16(sb + OFF_AH * 2, pAhi + ko);
        cpa16(sb + OFF_AL * 2, pAlo + ko);
        cpa16(sb + OFF_BH * 2, pBhi + ko);
        cpa16(sb + OFF_BL * 2, pBlo + ko);
        cpa_commit();
    }

    for (int c = 0; c < NCHUNK; c++) {
        cpa_wait1();
        __syncthreads();

        if (c + 2 < NCHUNK) {
            int slot = (c + 2) % NSTAGE;
            uint32_t sb = su + (uint32_t)slot * STAGE_B + sstore;
            int ko = (c + 2) * 16;
            cpa16(sb + OFF_AH * 2, pAhi + ko);
            cpa16(sb + OFF_AL * 2, pAlo + ko);
            cpa16(sb + OFF_BH * 2, pBhi + ko);
            cpa16(sb + OFF_BL * 2, pBlo + ko);
        }
        cpa_commit();

        const uint32_t sb = su + (uint32_t)(c % NSTAGE) * STAGE_B;
        uint32_t bh[8], bl[8];
        ldsm4(sb + OFF_BH * 2 + bAddr, bh[0], bh[1], bh[2], bh[3]);
        ldsm4(sb + OFF_BH * 2 + bAddr + 16 * RSTR * 2, bh[4], bh[5], bh[6], bh[7]);
        ldsm4(sb + OFF_BL * 2 + bAddr, bl[0], bl[1], bl[2], bl[3]);
        ldsm4(sb + OFF_BL * 2 + bAddr + 16 * RSTR * 2, bl[4], bl[5], bl[6], bl[7]);

#pragma unroll
        for (int mf = 0; mf < 4; mf++) {
            uint32_t a0, a1, a2, a3;
            ldsm4(sb + OFF_AH * 2 + aAddr + mf * 16 * RSTR * 2, a0, a1, a2, a3);
#pragma unroll
            for (int nf = 0; nf < 4; nf++)
                mma_bf16(acc[mf][nf][0], acc[mf][nf][1], acc[mf][nf][2], acc[mf][nf][3],
                         a0, a1, a2, a3, bh[nf * 2], bh[nf * 2 + 1]);
#pragma unroll
            for (int nf = 0; nf < 4; nf++)
                mma_bf16(acc[mf][nf][0], acc[mf][nf][1], acc[mf][nf][2], acc[mf][nf][3],
                         a0, a1, a2, a3, bl[nf * 2], bl[nf * 2 + 1]);
            ldsm4(sb + OFF_AL * 2 + aAddr + mf * 16 * RSTR * 2, a0, a1, a2, a3);
#pragma unroll
            for (int nf = 0; nf < 4; nf++)
                mma_bf16(acc[mf][nf][0], acc[mf][nf][1], acc[mf][nf][2], acc[mf][nf][3],
                         a0, a1, a2, a3, bh[nf * 2], bh[nf * 2 + 1]);
        }
        __syncthreads();
    }

#pragma unroll
    for (int mf = 0; mf < 4; mf++) {
#pragma unroll
        for (int nf = 0; nf < 4; nf++) {
            int m0 = bm + wm * 64 + mf * 16 + (lane >> 2);
            int col = bn + wn * 32 + nf * 8 + (lane & 3) * 2;
            float2 bb = *(const float2*)&bias[col];
            float2 v0, v1;
            v0.x = acc[mf][nf][0] + bb.x;
            v0.y = acc[mf][nf][1] + bb.y;
            v1.x = acc[mf][nf][2] + bb.x;
            v1.y = acc[mf][nf][3] + bb.y;
            if (MODE == 0) {
                int part = col >> 10;
                int h = (col >> 6) & (HEADS - 1);
                int d = col & 63;
                float* base = &g_qkv[(((size_t)part * HEADS + h) * NTOK) * HD + d];
                *(float2*)(base + (size_t)m0 * HD) = v0;
                *(float2*)(base + (size_t)(m0 + 8) * HD) = v1;
            } else {
                *(float2*)&Cout[(size_t)m0 * Nc + col] = v0;
                *(float2*)&Cout[(size_t)(m0 + 8) * Nc + col] = v1;
            }
        }
    }
}

// ---------------------------------------------------------------------------
// LayerNorm + bf16 hi/lo split of q, k, and passthrough split of v.
// ---------------------------------------------------------------------------
__global__ void __launch_bounds__(256)
ln2_kernel(const float* __restrict__ qg, const float* __restrict__ qb,
           const float* __restrict__ kg, const float* __restrict__ kb)
{
    const int HN = HEADS * NTOK;
    int warp = (blockIdx.x * blockDim.x + threadIdx.x) >> 5;
    int lane = threadIdx.x & 31;
    if (warp >= 3 * HN) return;

    const float* v = g_qkv + (size_t)warp * HD;
    float2 x = *(const float2*)&v[lane * 2];
    int part = warp / HN;
    int local = warp - part * HN;

    if (part < 2) {
        float s = x.x + x.y;
#pragma unroll
        for (int o = 16; o; o >>= 1) s += __shfl_xor_sync(0xffffffffu, s, o);
        float mu = s * (1.f / 64.f);
        float dx = x.x - mu, dy = x.y - mu;
        float ss = dx * dx + dy * dy;
#pragma unroll
        for (int o = 16; o; o >>= 1) ss += __shfl_xor_sync(0xffffffffu, ss, o);
        float rstd = rsqrtf(ss * (1.f / 64.f) + 1e-6f);
        const float* g = (part == 0) ? qg : kg;
        const float* b = (part == 0) ? qb : kb;
        x.x = dx * rstd * g[lane * 2] + b[lane * 2];
        x.y = dy * rstd * g[lane * 2 + 1] + b[lane * 2 + 1];
    }

    __nv_bfloat16* hi = (part == 0) ? g_qhi : (part == 1) ? g_khi : g_vhi;
    __nv_bfloat16* lo = (part == 0) ? g_qlo : (part == 1) ? g_klo : g_vlo;
    __nv_bfloat16 h0 = __float2bfloat16_rn(x.x);
    __nv_bfloat16 h1 = __float2bfloat16_rn(x.y);
    __nv_bfloat16 l0 = __float2bfloat16_rn(x.x - __bfloat162float(h0));
    __nv_bfloat16 l1 = __float2bfloat16_rn(x.y - __bfloat162float(h1));
    __nv_bfloat162 ph; ph.x = h0; ph.y = h1;
    __nv_bfloat162 pl; pl.x = l0; pl.y = l1;
    *(__nv_bfloat162*)&hi[(size_t)local * HD + lane * 2] = ph;
    *(__nv_bfloat162*)&lo[(size_t)local * HD + lane * 2] = pl;
}

// ---------------------------------------------------------------------------
// HMMA flash attention v4: KV-split x2 AND 2 CTAs/SM.
// Q hi+lo in smem (low registers), K/V tiles via cp.async double buffer.
// Epilogue stores UNNORMALIZED fp32 partials + row sums (combine divides).
// ---------------------------------------------------------------------------
#define AST 72
#define QLO_OFF 0
#define QHI_OFF (224 * AST)                       // 16128
#define KARR (KT * AST)                           // 2304
#define TILE_ELEMS (4 * KARR)                     // 9216
#define TILE_OFF (2 * 224 * AST)                  // 32256
#define BIAS_OFF (TILE_OFF + 2 * TILE_ELEMS)      // 50688 elems
#define AT_SMEM_BYTES (BIAS_OFF * 2 + 2 * KT * 4)   // 101632

__global__ void __launch_bounds__(224, 2)
attn8_kernel()
{
    extern __shared__ __nv_bfloat16 smb2[];
    const uint32_t su = smem_u32(smb2);

    const int s = blockIdx.x, h = blockIdx.y, split = blockIdx.z;
    const int tid = threadIdx.x, wid = tid >> 5, lane = tid & 31;
    const int m0 = wid * 32;

    const __nv_bfloat16* qh  = g_qhi + ((size_t)h * NTOK + (size_t)s * PTOK) * HD;
    const __nv_bfloat16* qlg = g_qlo + ((size_t)h * NTOK + (size_t)s * PTOK) * HD;
    const __nv_bfloat16* kh = g_khi + (size_t)h * NTOK * HD;
    const __nv_bfloat16* kl = g_klo + (size_t)h * NTOK * HD;
    const __nv_bfloat16* vh = g_vhi + (size_t)h * NTOK * HD;
    const __nv_bfloat16* vl = g_vlo + (size_t)h * NTOK * HD;

    // Q hi + lo -> smem (row per thread, clamp rows >= 196)
    {
        int row = tid;
        int srcr = row < PTOK ? row : PTOK - 1;
        const uint4* pl = (const uint4*)(qlg + (size_t)srcr * HD);
        const uint4* ph = (const uint4*)(qh + (size_t)srcr * HD);
#pragma unroll
        for (int j = 0; j < 8; j++) {
            *(uint4*)&smb2[QLO_OFF + row * AST + j * 8] = pl[j];
            *(uint4*)&smb2[QHI_OFF + row * AST + j * 8] = ph[j];
        }
    }

    float o[2][8][4];
    float lsum[2][2];
#pragma unroll
    for (int mf = 0; mf < 2; mf++) {
        lsum[mf][0] = 0.f; lsum[mf][1] = 0.f;
#pragma unroll
        for (int nf = 0; nf < 8; nf++)
#pragma unroll
            for (int e = 0; e < 4; e++) o[mf][nf][e] = 0.f;
    }

    const int pbase = s * MKPAD + split * KVSPL;

    // per-lane ldsm fragment addresses (bytes; tile buffer offset added later)
    const uint32_t kaddr = su + 2 * (TILE_OFF
        + ((lane & 7) + ((lane >> 4) & 1) * 8) * AST + ((lane >> 3) & 1) * 8);
    const uint32_t vaddr = su + 2 * (TILE_OFF + 2 * KARR
        + ((lane & 7) + ((lane >> 3) & 1) * 8) * AST + ((lane >> 4) & 1) * 8);
    const uint32_t qladdr = su + 2 * (QLO_OFF + (m0 + (lane & 15)) * AST + (lane >> 4) * 8);
    const uint32_t qhaddr = su + 2 * (QHI_OFF + (m0 + (lane & 15)) * AST + (lane >> 4) * 8);

    // issue gathered tile t1 into buffer b via cp.async
    auto issue_tile = [&](int t1, int b) {
        const int ibase = pbase + t1 * KT;
#pragma unroll
        for (int it = 0; it < 5; it++) {
            int slot = tid + it * 224;
            if (slot < 1024) {
                int a = slot >> 8, r = (slot >> 3) & 31, seg = slot & 7;
                int tok = g_gidx2[ibase + r];
                const __nv_bfloat16* bp = (a == 0) ? kh : (a == 1) ? kl
                                         : (a == 2) ? vh : vl;
                cpa16(su + 2 * (TILE_OFF + b * TILE_ELEMS + a * KARR + r * AST + seg * 8),
                      bp + (size_t)tok * HD + seg * 8);
            }
        }
        if (tid < 8)
            cpa16(su + 2 * BIAS_OFF + b * 128 + tid * 16, &g_bias2[ibase + tid * 4]);
    };

    issue_tile(0, 0);
    cpa_commit();

    for (int t = 0; t < NT_S; t++) {
        cpa_wait0();                    // tile t's copies complete
        __syncthreads();                // all warps done computing tile t-1

        if (t + 1 < NT_S) issue_tile(t + 1, (t + 1) & 1);
        cpa_commit();

        const uint32_t boff = (uint32_t)(t & 1) * TILE_ELEMS * 2;
        const float* Bs = (const float*)(smb2 + BIAS_OFF) + (t & 1) * 32;

        // ---- QK: 3-product bf16 split (Q hi/lo from smem via ldsm) ----
        float sc[2][4][4];
#pragma unroll
        for (int mf = 0; mf < 2; mf++)
#pragma unroll
            for (int nf = 0; nf < 4; nf++)
#pragma unroll
                for (int e = 0; e < 4; e++) sc[mf][nf][e] = 0.f;

#pragma unroll
        for (int kf = 0; kf < 4; kf++) {
            uint32_t bh0[4], bh1[4], bl0[4], bl1[4];
            ldsm4(kaddr + boff + kf * 32, bh0[0], bh0[1], bh0[2], bh0[3]);
            ldsm4(kaddr + boff + kf * 32 + 16 * AST * 2, bh1[0], bh1[1], bh1[2], bh1[3]);
            ldsm4(kaddr + boff + KARR * 2 + kf * 32, bl0[0], bl0[1], bl0[2], bl0[3]);
            ldsm4(kaddr + boff + KARR * 2 + kf * 32 + 16 * AST * 2,
                  bl1[0], bl1[1], bl1[2], bl1[3]);
#pragma unroll
            for (int mf = 0; mf < 2; mf++) {
                uint32_t q0, q1, q2, q3;
                ldsm4(qhaddr + mf * 16 * AST * 2 + kf * 32, q0, q1, q2, q3);
                mma_bf16(sc[mf][0][0], sc[mf][0][1], sc[mf][0][2], sc[mf][0][3],
                         q0, q1, q2, q3, bh0[0], bh0[1]);
                mma_bf16(sc[mf][1][0], sc[mf][1][1], sc[mf][1][2], sc[mf][1][3],
                         q0, q1, q2, q3, bh0[2], bh0[3]);
                mma_bf16(sc[mf][2][0], sc[mf][2][1], sc[mf][2][2], sc[mf][2][3],
                         q0, q1, q2, q3, bh1[0], bh1[1]);
                mma_bf16(sc[mf][3][0], sc[mf][3][1], sc[mf][3][2], sc[mf][3][3],
                         q0, q1, q2, q3, bh1[2], bh1[3]);
                mma_bf16(sc[mf][0][0], sc[mf][0][1], sc[mf][0][2], sc[mf][0][3],
                         q0, q1, q2, q3, bl0[0], bl0[1]);
                mma_bf16(sc[mf][1][0], sc[mf][1][1], sc[mf][1][2], sc[mf][1][3],
                         q0, q1, q2, q3, bl0[2], bl0[3]);
                mma_bf16(sc[mf][2][0], sc[mf][2][1], sc[mf][2][2], sc[mf][2][3],
                         q0, q1, q2, q3, bl1[0], bl1[1]);
                mma_bf16(sc[mf][3][0], sc[mf][3][1], sc[mf][3][2], sc[mf][3][3],
                         q0, q1, q2, q3, bl1[2], bl1[3]);
                ldsm4(qladdr + mf * 16 * AST * 2 + kf * 32, q0, q1, q2, q3);
                mma_bf16(sc[mf][0][0], sc[mf][0][1], sc[mf][0][2], sc[mf][0][3],
                         q0, q1, q2, q3, bh0[0], bh0[1]);
                mma_bf16(sc[mf][1][0], sc[mf][1][1], sc[mf][1][2], sc[mf][1][3],
                         q0, q1, q2, q3, bh0[2], bh0[3]);
                mma_bf16(sc[mf][2][0], sc[mf][2][1], sc[mf][2][2], sc[mf][2][3],
                         q0, q1, q2, q3, bh1[0], bh1[1]);
                mma_bf16(sc[mf][3][0], sc[mf][3][1], sc[mf][3][2], sc[mf][3][3],
                         q0, q1, q2, q3, bh1[2], bh1[3]);
            }
        }

        // ---- softmax weights + P split ----
        uint32_t phi[2][2][4], plo[2][2][4];
#pragma unroll
        for (int mf = 0; mf < 2; mf++) {
#pragma unroll
            for (int nf = 0; nf < 4; nf++) {
                float2 bb = *(const float2*)&Bs[nf * 8 + (lane & 3) * 2];
                float p0 = __expf(fmaf(sc[mf][nf][0], 0.125f, bb.x));
                float p1 = __expf(fmaf(sc[mf][nf][1], 0.125f, bb.y));
                float p2 = __expf(fmaf(sc[mf][nf][2], 0.125f, bb.x));
                float p3 = __expf(fmaf(sc[mf][nf][3], 0.125f, bb.y));
                lsum[mf][0] += p0 + p1;
                lsum[mf][1] += p2 + p3;
                uint32_t h01 = pack_bf16(p0, p1);
                uint32_t h23 = pack_bf16(p2, p3);
                __nv_bfloat162 hv01 = *(__nv_bfloat162*)&h01;
                __nv_bfloat162 hv23 = *(__nv_bfloat162*)&h23;
                uint32_t l01 = pack_bf16(p0 - __bfloat162float(hv01.x),
                                         p1 - __bfloat162float(hv01.y));
                uint32_t l23 = pack_bf16(p2 - __bfloat162float(hv23.x),
                                         p3 - __bfloat162float(hv23.y));
                int kf2 = nf >> 1, hf = (nf & 1) * 2;
                phi[mf][kf2][hf] = h01; phi[mf][kf2][hf + 1] = h23;
                plo[mf][kf2][hf] = l01; plo[mf][kf2][hf + 1] = l23;
            }
        }

        // ---- PV: 3-product split, V via ldsm.trans ----
#pragma unroll
        for (int kf = 0; kf < 2; kf++) {
            uint32_t vhf[16], vlf[16];
#pragma unroll
            for (int db = 0; db < 4; db++) {
                ldsm4t(vaddr + boff + kf * (16 * AST * 2) + db * 32,
                       vhf[db * 4], vhf[db * 4 + 1], vhf[db * 4 + 2], vhf[db * 4 + 3]);
                ldsm4t(vaddr + boff + KARR * 2 + kf * (16 * AST * 2) + db * 32,
                       vlf[db * 4], vlf[db * 4 + 1], vlf[db * 4 + 2], vlf[db * 4 + 3]);
            }
#pragma unroll
            for (int mf = 0; mf < 2; mf++) {
#pragma unroll
                for (int nfd = 0; nfd < 8; nfd++) {
                    int vi = (nfd >> 1) * 4 + (nfd & 1) * 2;
                    mma_bf16(o[mf][nfd][0], o[mf][nfd][1], o[mf][nfd][2], o[mf][nfd][3],
                             phi[mf][kf][0], phi[mf][kf][1], phi[mf][kf][2], phi[mf][kf][3],
                             vhf[vi], vhf[vi + 1]);
                    mma_bf16(o[mf][nfd][0], o[mf][nfd][1], o[mf][nfd][2], o[mf][nfd][3],
                             phi[mf][kf][0], phi[mf][kf][1], phi[mf][kf][2], phi[mf][kf][3],
                             vlf[vi], vlf[vi + 1]);
                    mma_bf16(o[mf][nfd][0], o[mf][nfd][1], o[mf][nfd][2], o[mf][nfd][3],
                             plo[mf][kf][0], plo[mf][kf][1], plo[mf][kf][2], plo[mf][kf][3],
                             vhf[vi], vhf[vi + 1]);
                }
            }
        }
    }

    // reduce l over the 4 lanes sharing each row
#pragma unroll
    for (int mf = 0; mf < 2; mf++) {
#pragma unroll
        for (int j = 0; j < 2; j++) {
            float v = lsum[mf][j];
            v += __shfl_xor_sync(0xffffffffu, v, 1);
            v += __shfl_xor_sync(0xffffffffu, v, 2);
            lsum[mf][j] = v;
        }
    }

    // epilogue: store UNNORMALIZED partials (fp32) + row sums
    {
        int r = lane >> 2, c2 = (lane & 3) * 2;
        const size_t rrbase = ((size_t)(split * SFR + s) * HEADS + h) * PTOK;
#pragma unroll
        for (int mf = 0; mf < 2; mf++) {
            int rowq0 = m0 + mf * 16 + r;
            int rowq1 = rowq0 + 8;
            if (rowq0 < PTOK) {
                float* dst = g_pacc + (rrbase + rowq0) * HD + c2;
#pragma unroll
                for (int nfd = 0; nfd < 8; nfd++) {
                    float2 v; v.x = o[mf][nfd][0]; v.y = o[mf][nfd][1];
                    *(float2*)(dst + nfd * 8) = v;
                }
                if ((lane & 3) == 0) g_pl[rrbase + rowq0] = lsum[mf][0];
            }
            if (rowq1 < PTOK) {
                float* dst = g_pacc + (rrbase + rowq1) * HD + c2;
#pragma unroll
                for (int nfd = 0; nfd < 8; nfd++) {
                    float2 v; v.x = o[mf][nfd][2]; v.y = o[mf][nfd][3];
                    *(float2*)(dst + nfd * 8) = v;
                }
                if ((lane & 3) == 0) g_pl[rrbase + rowq1] = lsum[mf][1];
            }
        }
    }
}

// ---------------------------------------------------------------------------
// Combine split partials: (n0+n1)/(l0+l1) -> bf16 hi/lo token-major planes.
// ---------------------------------------------------------------------------
__global__ void __launch_bounds__(256)
combine_kernel()
{
    int idx = blockIdx.x * blockDim.x + threadIdx.x;
    const int total = SFR * HEADS * PTOK * (HD / 4);
    if (idx >= total) return;
    int c4 = idx & 15;
    int shp = idx >> 4;
    size_t row0 = shp;
    size_t row1 = (size_t)SFR * HEADS * PTOK + shp;
    float4 a = ((const float4*)(g_pacc + row0 * HD))[c4];
    float4 b = ((const float4*)(g_pacc + row1 * HD))[c4];
    float inv = 1.f / (g_pl[row0] + g_pl[row1]);
    float f0 = (a.x + b.x) * inv;
    float f1 = (a.y + b.y) * inv;
    float f2 = (a.z + b.z) * inv;
    float f3 = (a.w + b.w) * inv;
    int p = shp % PTOK;
    int sh = shp / PTOK;
    int hh = sh % HEADS;
    int ss = sh / HEADS;
    size_t base = (size_t)(ss * PTOK + p) * CDIM + hh * HD + c4 * 4;
    uint32_t h01 = pack_bf16(f0, f1);
    uint32_t h23 = pack_bf16(f2, f3);
    __nv_bfloat162 hv01 = *(__nv_bfloat162*)&h01;
    __nv_bfloat162 hv23 = *(__nv_bfloat162*)&h23;
    uint32_t l01 = pack_bf16(f0 - __bfloat162float(hv01.x),
                             f1 - __bfloat162float(hv01.y));
    uint32_t l23 = pack_bf16(f2 - __bfloat162float(hv23.x),
                             f3 - __bfloat162float(hv23.y));
    *(uint32_t*)&g_ahi[base] = h01;
    *(uint32_t*)&g_ahi[base + 2] = h23;
    *(uint32_t*)&g_alo[base] = l01;
    *(uint32_t*)&g_alo[base + 2] = l23;
}

// ---------------------------------------------------------------------------
extern "C" void kernel_launch(void* const* d_in, const int* in_sizes, int n_in,
                              void* d_out, int out_size)
{
    const float* x     = (const float*)d_in[0];
    const float* Wqkv  = (const float*)d_in[1];
    const float* bqkv  = (const float*)d_in[2];
    const float* qg    = (const float*)d_in[3];
    const float* qb    = (const float*)d_in[4];
    const float* kg    = (const float*)d_in[5];
    const float* kb    = (const float*)d_in[6];
    const float* Wproj = (const float*)d_in[7];
    const float* bproj = (const float*)d_in[8];
    const int*   gidx  = (const int*)d_in[9];
    const float* abias = (const float*)d_in[10];
    float* out = (float*)d_out;

    static int attr_set = 0;
    if (!attr_set) {
        cudaFuncSetAttribute(hmma_gemm_kernel<0>,
                             cudaFuncAttributeMaxDynamicSharedMemorySize, GEMM_SMEM);
        cudaFuncSetAttribute(hmma_gemm_kernel<1>,
                             cudaFuncAttributeMaxDynamicSharedMemorySize, GEMM_SMEM);
        cudaFuncSetAttribute(attn8_kernel,
                             cudaFuncAttributeMaxDynamicSharedMemorySize, AT_SMEM_BYTES);
        attr_set = 1;
    }

    const int n4 = NTOK * KDIM / 4;

    // 0) prep
    split_kernel<<<n4 / 256, 256>>>(x, n4);
    pad_kernel<<<(SFR * MKPAD + 255) / 256, 256>>>(gidx, abias);
    wsplit_kernel<0><<<dim3(NQKV / 32, KDIM / 32), 256>>>(Wqkv, NQKV);
    wsplit_kernel<1><<<dim3(1024 / 32, KDIM / 32), 256>>>(Wproj, 1024);

    // 1) QKV GEMM -> g_qkv fp32 (R7-exact)
    hmma_gemm_kernel<0><<<dim3(NQKV / 128, NTOK / 128), 256, GEMM_SMEM>>>(
        bqkv, nullptr, NQKV);

    // 2) LayerNorm + bf16 hi/lo split of q/k/v
    {
        int nvec = 3 * HEADS * NTOK;
        ln2_kernel<<<(nvec * 32 + 255) / 256, 256>>>(qg, qb, kg, kb);
    }

    // 3) HMMA flash attention, KV-split x2, 2 CTAs/SM -> fp32 partials
    attn8_kernel<<<dim3(SFR, HEADS, NSPL), 224, AT_SMEM_BYTES>>>();

    // 3b) combine partials -> g_ahi/g_alo
    {
        const int total = SFR * HEADS * PTOK * (HD / 4);
        combine_kernel<<<(total + 255) / 256, 256>>>();
    }

    // 4) proj GEMM -> d_out (R7-exact)
    hmma_gemm_kernel<1><<<dim3(1024 / 128, NTOK / 128), 256, GEMM_SMEM>>>(
        bproj, out, 1024);
}

// round 13
// speedup vs baseline: 1.0900x; 1.0338x over previous
#include <cuda_runtime.h>
#include <cuda_bf16.h>
#include <cstdint>

#define NTOK 6272
#define CDIM 1024
#define HEADS 16
#define HD 64
#define SFR 32
#define PTOK 196
#define MKV 1960
#define KT 32
#define MKPAD 1984
#define NSPL 2
#define NT_S 31
#define KVSPL (NT_S * KT)

#define KDIM 1024
#define NQKV 3072

// Scratch (no allocations anywhere)
__device__ __nv_bfloat16 g_ahi[(size_t)NTOK * KDIM];
__device__ __nv_bfloat16 g_alo[(size_t)NTOK * KDIM];
__device__ __nv_bfloat16 g_wqhi[(size_t)NQKV * KDIM];
__device__ __nv_bfloat16 g_wqlo[(size_t)NQKV * KDIM];
__device__ __nv_bfloat16 g_wphi[(size_t)1024 * KDIM];
__device__ __nv_bfloat16 g_wplo[(size_t)1024 * KDIM];
__device__ __nv_bfloat16 g_qhi[(size_t)HEADS * NTOK * HD];
__device__ __nv_bfloat16 g_qlo[(size_t)HEADS * NTOK * HD];
__device__ __nv_bfloat16 g_khi[(size_t)HEADS * NTOK * HD];
__device__ __nv_bfloat16 g_klo[(size_t)HEADS * NTOK * HD];
__device__ __nv_bfloat16 g_vhi[(size_t)HEADS * NTOK * HD];
__device__ __nv_bfloat16 g_vlo[(size_t)HEADS * NTOK * HD];
__device__ int   g_gidx2[SFR * MKPAD];
__device__ float g_bias2[SFR * MKPAD];
__device__ float g_pacc[(size_t)NSPL * SFR * HEADS * PTOK * HD];
__device__ float g_pl[NSPL * SFR * HEADS * PTOK];

// ---------------------------------------------------------------------------
// helpers
// ---------------------------------------------------------------------------
__device__ __forceinline__ uint32_t smem_u32(const void* p) {
    uint32_t a;
    asm("{ .reg .u64 t; cvta.to.shared.u64 t, %1; cvt.u32.u64 %0, t; }"
        : "=r"(a) : "l"(p));
    return a;
}
__device__ __forceinline__ void ldsm4(uint32_t addr, uint32_t& r0, uint32_t& r1,
                                      uint32_t& r2, uint32_t& r3) {
    asm volatile("ldmatrix.sync.aligned.m8n8.x4.shared.b16 {%0,%1,%2,%3}, [%4];"
                 : "=r"(r0), "=r"(r1), "=r"(r2), "=r"(r3) : "r"(addr));
}
__device__ __forceinline__ void ldsm4t(uint32_t addr, uint32_t& r0, uint32_t& r1,
                                       uint32_t& r2, uint32_t& r3) {
    asm volatile("ldmatrix.sync.aligned.m8n8.x4.trans.shared.b16 {%0,%1,%2,%3}, [%4];"
                 : "=r"(r0), "=r"(r1), "=r"(r2), "=r"(r3) : "r"(addr));
}
__device__ __forceinline__ void mma_bf16(float& d0, float& d1, float& d2, float& d3,
                                         uint32_t a0, uint32_t a1, uint32_t a2, uint32_t a3,
                                         uint32_t b0, uint32_t b1) {
    asm volatile(
        "mma.sync.aligned.m16n8k16.row.col.f32.bf16.bf16.f32 "
        "{%0,%1,%2,%3}, {%4,%5,%6,%7}, {%8,%9}, {%0,%1,%2,%3};"
        : "+f"(d0), "+f"(d1), "+f"(d2), "+f"(d3)
        : "r"(a0), "r"(a1), "r"(a2), "r"(a3), "r"(b0), "r"(b1));
}
__device__ __forceinline__ uint32_t pack_bf16(float a, float b) {
    __nv_bfloat162 t;
    t.x = __float2bfloat16_rn(a);
    t.y = __float2bfloat16_rn(b);
    return *(uint32_t*)&t;
}
__device__ __forceinline__ void cpa16(uint32_t dst, const void* src) {
    asm volatile("cp.async.cg.shared.global [%0], [%1], 16;"
                 :: "r"(dst), "l"(src) : "memory");
}
__device__ __forceinline__ void cpa_commit() {
    asm volatile("cp.async.commit_group;" ::: "memory");
}
__device__ __forceinline__ void cpa_wait1() {
    asm volatile("cp.async.wait_group 1;" ::: "memory");
}

// ---------------------------------------------------------------------------
// Split fp32 -> bf16 hi/lo planes into g_ahi/g_alo (same layout)
// ---------------------------------------------------------------------------
__global__ void __launch_bounds__(256)
split_kernel(const float* __restrict__ src, int n4)
{
    int i = blockIdx.x * blockDim.x + threadIdx.x;
    if (i >= n4) return;
    float4 a = ((const float4*)src)[i];
    __nv_bfloat16 h0 = __float2bfloat16_rn(a.x);
    __nv_bfloat16 h1 = __float2bfloat16_rn(a.y);
    __nv_bfloat16 h2 = __float2bfloat16_rn(a.z);
    __nv_bfloat16 h3 = __float2bfloat16_rn(a.w);
    __nv_bfloat16 l0 = __float2bfloat16_rn(a.x - __bfloat162float(h0));
    __nv_bfloat16 l1 = __float2bfloat16_rn(a.y - __bfloat162float(h1));
    __nv_bfloat16 l2 = __float2bfloat16_rn(a.z - __bfloat162float(h2));
    __nv_bfloat16 l3 = __float2bfloat16_rn(a.w - __bfloat162float(h3));
    __nv_bfloat162 hh0; hh0.x = h0; hh0.y = h1;
    __nv_bfloat162 hh1; hh1.x = h2; hh1.y = h3;
    __nv_bfloat162 ll0; ll0.x = l0; ll0.y = l1;
    __nv_bfloat162 ll1; ll1.x = l2; ll1.y = l3;
    ((__nv_bfloat162*)g_ahi)[i * 2]     = hh0;
    ((__nv_bfloat162*)g_ahi)[i * 2 + 1] = hh1;
    ((__nv_bfloat162*)g_alo)[i * 2]     = ll0;
    ((__nv_bfloat162*)g_alo)[i * 2 + 1] = ll1;
}

// ---------------------------------------------------------------------------
// Pad/clamp gather indices and fold the static-max shift into the bias.
// ---------------------------------------------------------------------------
__global__ void __launch_bounds__(256)
pad_kernel(const int* __restrict__ gidx, const float* __restrict__ abias)
{
    int i = blockIdx.x * blockDim.x + threadIdx.x;
    if (i >= SFR * MKPAD) return;
    int s = i / MKPAD, j = i - s * MKPAD;
    int jj = (j < MKV) ? j : 0;
    g_gidx2[i] = gidx[s * MKV + jj];
    g_bias2[i] = (j < MKV) ? (abias[s * MKV + j] - 10.f) : -1e9f;
}

// ---------------------------------------------------------------------------
// Transpose + split: W [1024][N] fp32 -> hi/lo [N][1024] bf16
// ---------------------------------------------------------------------------
template <int WHICH>
__global__ void __launch_bounds__(256)
wsplit_kernel(const float* __restrict__ W, int N)
{
    __nv_bfloat16* hi = (WHICH == 0) ? g_wqhi : g_wphi;
    __nv_bfloat16* lo = (WHICH == 0) ? g_wqlo : g_wplo;
    __shared__ float t[32][33];
    int n0 = blockIdx.x * 32, k0 = blockIdx.y * 32;
    int tx = threadIdx.x & 31, ty = threadIdx.x >> 5;
#pragma unroll
    for (int r = 0; r < 4; r++)
        t[ty + r * 8][tx] = W[(size_t)(k0 + ty + r * 8) * N + n0 + tx];
    __syncthreads();
#pragma unroll
    for (int r = 0; r < 4; r++) {
        int n = ty + r * 8;
        float a = t[tx][n];
        __nv_bfloat16 h = __float2bfloat16_rn(a);
        __nv_bfloat16 l = __float2bfloat16_rn(a - __bfloat162float(h));
        size_t o = (size_t)(n0 + n) * KDIM + k0 + tx;
        hi[o] = h;
        lo[o] = l;
    }
}

// ---------------------------------------------------------------------------
// HMMA GEMM (R7-exact mainloop). MODE 0: fused LayerNorm + bf16 hi/lo split
// epilogue writing g_{q,k,v}{hi,lo} directly (g_qkv / ln kernel deleted).
// MODE 1: row-major C(+bias) -> Cout.
// ---------------------------------------------------------------------------
#define RSTR 24
#define TILE_E (128 * RSTR)
#define STAGE_E (4 * TILE_E)
#define STAGE_B (STAGE_E * 2)          // 24576 bytes
#define NSTAGE 3
#define GEMM_SMEM (NSTAGE * STAGE_B)   // 73728 bytes (>= 128*130*4 = 66560)
#define OFF_AH 0
#define OFF_AL TILE_E
#define OFF_BH (2 * TILE_E)
#define OFF_BL (3 * TILE_E)
#define LN_SS 130

template <int MODE>
__global__ void __launch_bounds__(256, 2)
hmma_gemm_kernel(const float* __restrict__ bias, float* __restrict__ Cout, int Nc,
                 const float* __restrict__ qg, const float* __restrict__ qb,
                 const float* __restrict__ kg, const float* __restrict__ kb)
{
    extern __shared__ __nv_bfloat16 smb[];
    const uint32_t su = smem_u32(smb);

    const __nv_bfloat16* Bhi = (MODE == 0) ? g_wqhi : g_wphi;
    const __nv_bfloat16* Blo = (MODE == 0) ? g_wqlo : g_wplo;

    const int tid = threadIdx.x;
    const int wid = tid >> 5;
    const int lane = tid & 31;
    const int wm = wid & 1;
    const int wn = wid >> 1;
    const int bm = blockIdx.y * 128;
    const int bn = blockIdx.x * 128;

    const int grow = tid >> 1;
    const int ghalf = tid & 1;
    const __nv_bfloat16* pAhi = g_ahi + (size_t)(bm + grow) * KDIM + ghalf * 8;
    const __nv_bfloat16* pAlo = g_alo + (size_t)(bm + grow) * KDIM + ghalf * 8;
    const __nv_bfloat16* pBhi = Bhi + (size_t)(bn + grow) * KDIM + ghalf * 8;
    const __nv_bfloat16* pBlo = Blo + (size_t)(bn + grow) * KDIM + ghalf * 8;
    const uint32_t sstore = (uint32_t)(grow * RSTR + ghalf * 8) * 2;

    const uint32_t aAddr = (uint32_t)((wm * 64 + (lane & 15)) * RSTR + (lane >> 4) * 8) * 2;
    const uint32_t bAddr = (uint32_t)((wn * 32 + (lane & 7) + ((lane >> 4) & 1) * 8) * RSTR
                                      + ((lane >> 3) & 1) * 8) * 2;

    float acc[4][4][4];
#pragma unroll
    for (int mf = 0; mf < 4; mf++)
#pragma unroll
        for (int nf = 0; nf < 4; nf++)
#pragma unroll
            for (int e = 0; e < 4; e++) acc[mf][nf][e] = 0.f;

    const int NCHUNK = KDIM / 16;      // 64

#pragma unroll
    for (int c = 0; c < 2; c++) {
        uint32_t sb = su + (uint32_t)c * STAGE_B + sstore;
        int ko = c * 16;
        cpa16(sb + OFF_AH * 2, pAhi + ko);
        cpa16(sb + OFF_AL * 2, pAlo + ko);
        cpa16(sb + OFF_BH * 2, pBhi + ko);
        cpa16(sb + OFF_BL * 2, pBlo + ko);
        cpa_commit();
    }

    for (int c = 0; c < NCHUNK; c++) {
        cpa_wait1();
        __syncthreads();

        if (c + 2 < NCHUNK) {
            int slot = (c + 2) % NSTAGE;
            uint32_t sb = su + (uint32_t)slot * STAGE_B + sstore;
            int ko = (c + 2) * 16;
            cpa16(sb + OFF_AH * 2, pAhi + ko);
            cpa16(sb + OFF_AL * 2, pAlo + ko);
            cpa16(sb + OFF_BH * 2, pBhi + ko);
            cpa16(sb + OFF_BL * 2, pBlo + ko);
        }
        cpa_commit();

        const uint32_t sb = su + (uint32_t)(c % NSTAGE) * STAGE_B;
        uint32_t bh[8], bl[8];
        ldsm4(sb + OFF_BH * 2 + bAddr, bh[0], bh[1], bh[2], bh[3]);
        ldsm4(sb + OFF_BH * 2 + bAddr + 16 * RSTR * 2, bh[4], bh[5], bh[6], bh[7]);
        ldsm4(sb + OFF_BL * 2 + bAddr, bl[0], bl[1], bl[2], bl[3]);
        ldsm4(sb + OFF_BL * 2 + bAddr + 16 * RSTR * 2, bl[4], bl[5], bl[6], bl[7]);

#pragma unroll
        for (int mf = 0; mf < 4; mf++) {
            uint32_t a0, a1, a2, a3;
            ldsm4(sb + OFF_AH * 2 + aAddr + mf * 16 * RSTR * 2, a0, a1, a2, a3);
#pragma unroll
            for (int nf = 0; nf < 4; nf++)
                mma_bf16(acc[mf][nf][0], acc[mf][nf][1], acc[mf][nf][2], acc[mf][nf][3],
                         a0, a1, a2, a3, bh[nf * 2], bh[nf * 2 + 1]);
#pragma unroll
            for (int nf = 0; nf < 4; nf++)
                mma_bf16(acc[mf][nf][0], acc[mf][nf][1], acc[mf][nf][2], acc[mf][nf][3],
                         a0, a1, a2, a3, bl[nf * 2], bl[nf * 2 + 1]);
            ldsm4(sb + OFF_AL * 2 + aAddr + mf * 16 * RSTR * 2, a0, a1, a2, a3);
#pragma unroll
            for (int nf = 0; nf < 4; nf++)
                mma_bf16(acc[mf][nf][0], acc[mf][nf][1], acc[mf][nf][2], acc[mf][nf][3],
                         a0, a1, a2, a3, bh[nf * 2], bh[nf * 2 + 1]);
        }
        __syncthreads();
    }

    if (MODE == 1) {
#pragma unroll
        for (int mf = 0; mf < 4; mf++) {
#pragma unroll
            for (int nf = 0; nf < 4; nf++) {
                int m0 = bm + wm * 64 + mf * 16 + (lane >> 2);
                int col = bn + wn * 32 + nf * 8 + (lane & 3) * 2;
                float2 bb = *(const float2*)&bias[col];
                float2 v0, v1;
                v0.x = acc[mf][nf][0] + bb.x;
                v0.y = acc[mf][nf][1] + bb.y;
                v1.x = acc[mf][nf][2] + bb.x;
                v1.y = acc[mf][nf][3] + bb.y;
                *(float2*)&Cout[(size_t)m0 * Nc + col] = v0;
                *(float2*)&Cout[(size_t)(m0 + 8) * Nc + col] = v1;
            }
        }
    } else {
        // ---- fused LayerNorm + bf16 hi/lo split epilogue ----
        float* S = (float*)smb;
        // stage acc(+bias) tile into smem: [128 rows][LN_SS]
#pragma unroll
        for (int mf = 0; mf < 4; mf++) {
#pragma unroll
            for (int nf = 0; nf < 4; nf++) {
                int ml = wm * 64 + mf * 16 + (lane >> 2);
                int cl = wn * 32 + nf * 8 + (lane & 3) * 2;
                float2 bb = *(const float2*)&bias[bn + cl];
                float2 v0, v1;
                v0.x = acc[mf][nf][0] + bb.x;
                v0.y = acc[mf][nf][1] + bb.y;
                v1.x = acc[mf][nf][2] + bb.x;
                v1.y = acc[mf][nf][3] + bb.y;
                *(float2*)&S[ml * LN_SS + cl] = v0;
                *(float2*)&S[(ml + 8) * LN_SS + cl] = v1;
            }
        }
        __syncthreads();

        const int row = tid & 127;
        const int hb = tid >> 7;               // which 64-col head-block
        const int gc = bn + hb * 64;
        const int part = gc >> 10;             // 0=q 1=k 2=v
        const int hh = (gc >> 6) & (HEADS - 1);
        const int m = bm + row;
        const float* Sr = &S[row * LN_SS + hb * 64];

        float sum = 0.f, sq = 0.f;
#pragma unroll
        for (int j = 0; j < 32; j++) {
            float2 t = *(const float2*)&Sr[j * 2];
            sum += t.x + t.y;
            sq += t.x * t.x + t.y * t.y;
        }
        float mu = 0.f, rstd = 1.f;
        const float* gp = (part == 0) ? qg : kg;
        const float* bp = (part == 0) ? qb : kb;
        if (part < 2) {
            mu = sum * (1.f / 64.f);
            float var = sq * (1.f / 64.f) - mu * mu;
            rstd = rsqrtf(var + 1e-6f);
        }
        __nv_bfloat16* hi = (part == 0) ? g_qhi : (part == 1) ? g_khi : g_vhi;
        __nv_bfloat16* lo = (part == 0) ? g_qlo : (part == 1) ? g_klo : g_vlo;
        size_t obase = ((size_t)hh * NTOK + m) * HD;

#pragma unroll
        for (int jj = 0; jj < 8; jj++) {
            float v[8];
#pragma unroll
            for (int k = 0; k < 4; k++) {
                float2 t = *(const float2*)&Sr[jj * 8 + k * 2];
                v[k * 2] = t.x;
                v[k * 2 + 1] = t.y;
            }
            if (part < 2) {
#pragma unroll
                for (int k = 0; k < 8; k++)
                    v[k] = (v[k] - mu) * rstd * gp[jj * 8 + k] + bp[jj * 8 + k];
            }
            uint32_t hw[4], lw[4];
#pragma unroll
            for (int k = 0; k < 4; k++) {
                hw[k] = pack_bf16(v[2 * k], v[2 * k + 1]);
                __nv_bfloat162 hv = *(__nv_bfloat162*)&hw[k];
                lw[k] = pack_bf16(v[2 * k] - __bfloat162float(hv.x),
                                  v[2 * k + 1] - __bfloat162float(hv.y));
            }
            *(uint4*)&hi[obase + jj * 8] = *(uint4*)hw;
            *(uint4*)&lo[obase + jj * 8] = *(uint4*)lw;
        }
    }
}

// ---------------------------------------------------------------------------
// HMMA flash attention, KV-split x2 (R10-exact WIN version).
// ---------------------------------------------------------------------------
#define AST 72
#define QLO_ELEMS (224 * AST)
#define KARR (KT * AST)
#define TILE_OFF QLO_ELEMS
#define BIAS_OFF (QLO_ELEMS + 4 * KARR)
#define AT_SMEM_BYTES (BIAS_OFF * 2 + KT * 4 + 16)

__global__ void __launch_bounds__(224, 1)
attn7_kernel()
{
    extern __shared__ __nv_bfloat16 smb2[];
    __nv_bfloat16* Qlo = smb2;
    __nv_bfloat16* Tile = smb2 + TILE_OFF;
    float* Bs = (float*)(smb2 + BIAS_OFF);
    const uint32_t su = smem_u32(smb2);

    const int s = blockIdx.x, h = blockIdx.y, split = blockIdx.z;
    const int tid = threadIdx.x, wid = tid >> 5, lane = tid & 31;
    const int m0 = wid * 32;

    const __nv_bfloat16* qh  = g_qhi + ((size_t)h * NTOK + (size_t)s * PTOK) * HD;
    const __nv_bfloat16* qlg = g_qlo + ((size_t)h * NTOK + (size_t)s * PTOK) * HD;
    const __nv_bfloat16* kh = g_khi + (size_t)h * NTOK * HD;
    const __nv_bfloat16* kl = g_klo + (size_t)h * NTOK * HD;
    const __nv_bfloat16* vh = g_vhi + (size_t)h * NTOK * HD;
    const __nv_bfloat16* vl = g_vlo + (size_t)h * NTOK * HD;

    // Qlo -> smem
    {
        int row = tid;
        int srcr = row < PTOK ? row : PTOK - 1;
        const uint4* p = (const uint4*)(qlg + (size_t)srcr * HD);
#pragma unroll
        for (int j = 0; j < 8; j++)
            *(uint4*)&Qlo[row * AST + j * 8] = p[j];
    }

    // Qhi fragments in registers
    uint32_t qf[2][4][4];
    {
        int r = lane >> 2, c2 = (lane & 3) * 2;
#pragma unroll
        for (int mf = 0; mf < 2; mf++) {
            int r0 = m0 + mf * 16 + r;
            int r1 = r0 + 8;
            if (r0 > PTOK - 1) r0 = PTOK - 1;
            if (r1 > PTOK - 1) r1 = PTOK - 1;
#pragma unroll
            for (int kf = 0; kf < 4; kf++) {
                int c0 = kf * 16 + c2;
                qf[mf][kf][0] = *(const uint32_t*)(qh + (size_t)r0 * HD + c0);
                qf[mf][kf][1] = *(const uint32_t*)(qh + (size_t)r1 * HD + c0);
                qf[mf][kf][2] = *(const uint32_t*)(qh + (size_t)r0 * HD + c0 + 8);
                qf[mf][kf][3] = *(const uint32_t*)(qh + (size_t)r1 * HD + c0 + 8);
            }
        }
    }

    float o[2][8][4];
    float lsum[2][2];
#pragma unroll
    for (int mf = 0; mf < 2; mf++) {
        lsum[mf][0] = 0.f; lsum[mf][1] = 0.f;
#pragma unroll
        for (int nf = 0; nf < 8; nf++)
#pragma unroll
            for (int e = 0; e < 4; e++) o[mf][nf][e] = 0.f;
    }

    const int pbase = s * MKPAD + split * KVSPL;

    const uint32_t kaddr = su + 2 * (TILE_OFF
        + ((lane & 7) + ((lane >> 4) & 1) * 8) * AST + ((lane >> 3) & 1) * 8);
    const uint32_t vaddr = su + 2 * (TILE_OFF + 2 * KARR
        + ((lane & 7) + ((lane >> 3) & 1) * 8) * AST + ((lane >> 4) & 1) * 8);
    const uint32_t qladdr = su + 2 * ((m0 + (lane & 15)) * AST + (lane >> 4) * 8);

    // prefetch tile 0 (register prefetch, R7-proven)
    uint4 pf[5];
    float pbias = 0.f;
#pragma unroll
    for (int it = 0; it < 5; it++) {
        int slot = tid + it * 224;
        if (slot < 1024) {
            int a = slot >> 8, r = (slot >> 3) & 31, seg = slot & 7;
            int tok = g_gidx2[pbase + r];
            const __nv_bfloat16* bp = (a == 0) ? kh : (a == 1) ? kl : (a == 2) ? vh : vl;
            pf[it] = *(const uint4*)(bp + (size_t)tok * HD + seg * 8);
        }
    }
    if (tid < KT) pbias = g_bias2[pbase + tid];

    for (int t = 0; t < NT_S; t++) {
        __syncthreads();
#pragma unroll
        for (int it = 0; it < 5; it++) {
            int slot = tid + it * 224;
            if (slot < 1024) {
                int a = slot >> 8, r = (slot >> 3) & 31, seg = slot & 7;
                *(uint4*)&Tile[a * KARR + r * AST + seg * 8] = pf[it];
            }
        }
        if (tid < KT) Bs[tid] = pbias;
        __syncthreads();

        if (t + 1 < NT_S) {
            int ib = pbase + (t + 1) * KT;
#pragma unroll
            for (int it = 0; it < 5; it++) {
                int slot = tid + it * 224;
                if (slot < 1024) {
                    int a = slot >> 8, r = (slot >> 3) & 31, seg = slot & 7;
                    int tok = g_gidx2[ib + r];
                    const __nv_bfloat16* bp = (a == 0) ? kh : (a == 1) ? kl
                                             : (a == 2) ? vh : vl;
                    pf[it] = *(const uint4*)(bp + (size_t)tok * HD + seg * 8);
                }
            }
            if (tid < KT) pbias = g_bias2[ib + tid];
        }

        // ---- QK: 3-product bf16 split ----
        float sc[2][4][4];
#pragma unroll
        for (int mf = 0; mf < 2; mf++)
#pragma unroll
            for (int nf = 0; nf < 4; nf++)
#pragma unroll
                for (int e = 0; e < 4; e++) sc[mf][nf][e] = 0.f;

#pragma unroll
        for (int kf = 0; kf < 4; kf++) {
            uint32_t bh0[4], bh1[4], bl0[4], bl1[4];
            ldsm4(kaddr + kf * 32, bh0[0], bh0[1], bh0[2], bh0[3]);
            ldsm4(kaddr + kf * 32 + 16 * AST * 2, bh1[0], bh1[1], bh1[2], bh1[3]);
            ldsm4(kaddr + KARR * 2 + kf * 32, bl0[0], bl0[1], bl0[2], bl0[3]);
            ldsm4(kaddr + KARR * 2 + kf * 32 + 16 * AST * 2, bl1[0], bl1[1], bl1[2], bl1[3]);
#pragma unroll
            for (int mf = 0; mf < 2; mf++) {
                uint32_t q0 = qf[mf][kf][0], q1 = qf[mf][kf][1];
                uint32_t q2 = qf[mf][kf][2], q3 = qf[mf][kf][3];
                mma_bf16(sc[mf][0][0], sc[mf][0][1], sc[mf][0][2], sc[mf][0][3],
                         q0, q1, q2, q3, bh0[0], bh0[1]);
                mma_bf16(sc[mf][1][0], sc[mf][1][1], sc[mf][1][2], sc[mf][1][3],
                         q0, q1, q2, q3, bh0[2], bh0[3]);
                mma_bf16(sc[mf][2][0], sc[mf][2][1], sc[mf][2][2], sc[mf][2][3],
                         q0, q1, q2, q3, bh1[0], bh1[1]);
                mma_bf16(sc[mf][3][0], sc[mf][3][1], sc[mf][3][2], sc[mf][3][3],
                         q0, q1, q2, q3, bh1[2], bh1[3]);
                mma_bf16(sc[mf][0][0], sc[mf][0][1], sc[mf][0][2], sc[mf][0][3],
                         q0, q1, q2, q3, bl0[0], bl0[1]);
                mma_bf16(sc[mf][1][0], sc[mf][1][1], sc[mf][1][2], sc[mf][1][3],
                         q0, q1, q2, q3, bl0[2], bl0[3]);
                mma_bf16(sc[mf][2][0], sc[mf][2][1], sc[mf][2][2], sc[mf][2][3],
                         q0, q1, q2, q3, bl1[0], bl1[1]);
                mma_bf16(sc[mf][3][0], sc[mf][3][1], sc[mf][3][2], sc[mf][3][3],
                         q0, q1, q2, q3, bl1[2], bl1[3]);
                uint32_t ql0, ql1, ql2, ql3;
                ldsm4(qladdr + mf * 16 * AST * 2 + kf * 32, ql0, ql1, ql2, ql3);
                mma_bf16(sc[mf][0][0], sc[mf][0][1], sc[mf][0][2], sc[mf][0][3],
                         ql0, ql1, ql2, ql3, bh0[0], bh0[1]);
                mma_bf16(sc[mf][1][0], sc[mf][1][1], sc[mf][1][2], sc[mf][1][3],
                         ql0, ql1, ql2, ql3, bh0[2], bh0[3]);
                mma_bf16(sc[mf][2][0], sc[mf][2][1], sc[mf][2][2], sc[mf][2][3],
                         ql0, ql1, ql2, ql3, bh1[0], bh1[1]);
                mma_bf16(sc[mf][3][0], sc[mf][3][1], sc[mf][3][2], sc[mf][3][3],
                         ql0, ql1, ql2, ql3, bh1[2], bh1[3]);
            }
        }

        // ---- softmax weights + P split ----
        uint32_t phi[2][2][4], plo[2][2][4];
#pragma unroll
        for (int mf = 0; mf < 2; mf++) {
#pragma unroll
            for (int nf = 0; nf < 4; nf++) {
                float2 bb = *(const float2*)&Bs[nf * 8 + (lane & 3) * 2];
                float p0 = __expf(fmaf(sc[mf][nf][0], 0.125f, bb.x));
                float p1 = __expf(fmaf(sc[mf][nf][1], 0.125f, bb.y));
                float p2 = __expf(fmaf(sc[mf][nf][2], 0.125f, bb.x));
                float p3 = __expf(fmaf(sc[mf][nf][3], 0.125f, bb.y));
                lsum[mf][0] += p0 + p1;
                lsum[mf][1] += p2 + p3;
                uint32_t h01 = pack_bf16(p0, p1);
                uint32_t h23 = pack_bf16(p2, p3);
                __nv_bfloat162 hv01 = *(__nv_bfloat162*)&h01;
                __nv_bfloat162 hv23 = *(__nv_bfloat162*)&h23;
                uint32_t l01 = pack_bf16(p0 - __bfloat162float(hv01.x),
                                         p1 - __bfloat162float(hv01.y));
                uint32_t l23 = pack_bf16(p2 - __bfloat162float(hv23.x),
                                         p3 - __bfloat162float(hv23.y));
                int kf2 = nf >> 1, hf = (nf & 1) * 2;
                phi[mf][kf2][hf] = h01; phi[mf][kf2][hf + 1] = h23;
                plo[mf][kf2][hf] = l01; plo[mf][kf2][hf + 1] = l23;
            }
        }

        // ---- PV: 3-product split, V via ldsm.trans ----
#pragma unroll
        for (int kf = 0; kf < 2; kf++) {
            uint32_t vhf[16], vlf[16];
#pragma unroll
            for (int db = 0; db < 4; db++) {
                ldsm4t(vaddr + kf * (16 * AST * 2) + db * 32,
                       vhf[db * 4], vhf[db * 4 + 1], vhf[db * 4 + 2], vhf[db * 4 + 3]);
                ldsm4t(vaddr + KARR * 2 + kf * (16 * AST * 2) + db * 32,
                       vlf[db * 4], vlf[db * 4 + 1], vlf[db * 4 + 2], vlf[db * 4 + 3]);
            }
#pragma unroll
            for (int mf = 0; mf < 2; mf++) {
#pragma unroll
                for (int nfd = 0; nfd < 8; nfd++) {
                    int vi = (nfd >> 1) * 4 + (nfd & 1) * 2;
                    mma_bf16(o[mf][nfd][0], o[mf][nfd][1], o[mf][nfd][2], o[mf][nfd][3],
                             phi[mf][kf][0], phi[mf][kf][1], phi[mf][kf][2], phi[mf][kf][3],
                             vhf[vi], vhf[vi + 1]);
                    mma_bf16(o[mf][nfd][0], o[mf][nfd][1], o[mf][nfd][2], o[mf][nfd][3],
                             phi[mf][kf][0], phi[mf][kf][1], phi[mf][kf][2], phi[mf][kf][3],
                             vlf[vi], vlf[vi + 1]);
                    mma_bf16(o[mf][nfd][0], o[mf][nfd][1], o[mf][nfd][2], o[mf][nfd][3],
                             plo[mf][kf][0], plo[mf][kf][1], plo[mf][kf][2], plo[mf][kf][3],
                             vhf[vi], vhf[vi + 1]);
                }
            }
        }
    }

    // reduce l over the 4 lanes sharing each row
#pragma unroll
    for (int mf = 0; mf < 2; mf++) {
#pragma unroll
        for (int j = 0; j < 2; j++) {
            float v = lsum[mf][j];
            v += __shfl_xor_sync(0xffffffffu, v, 1);
            v += __shfl_xor_sync(0xffffffffu, v, 2);
            lsum[mf][j] = v;
        }
    }

    // epilogue: store UNNORMALIZED partials (fp32) + row sums
    {
        int r = lane >> 2, c2 = (lane & 3) * 2;
        const size_t rrbase = ((size_t)(split * SFR + s) * HEADS + h) * PTOK;
#pragma unroll
        for (int mf = 0; mf < 2; mf++) {
            int rowq0 = m0 + mf * 16 + r;
            int rowq1 = rowq0 + 8;
            if (rowq0 < PTOK) {
                float* dst = g_pacc + (rrbase + rowq0) * HD + c2;
#pragma unroll
                for (int nfd = 0; nfd < 8; nfd++) {
                    float2 v; v.x = o[mf][nfd][0]; v.y = o[mf][nfd][1];
                    *(float2*)(dst + nfd * 8) = v;
                }
                if ((lane & 3) == 0) g_pl[rrbase + rowq0] = lsum[mf][0];
            }
            if (rowq1 < PTOK) {
                float* dst = g_pacc + (rrbase + rowq1) * HD + c2;
#pragma unroll
                for (int nfd = 0; nfd < 8; nfd++) {
                    float2 v; v.x = o[mf][nfd][2]; v.y = o[mf][nfd][3];
                    *(float2*)(dst + nfd * 8) = v;
                }
                if ((lane & 3) == 0) g_pl[rrbase + rowq1] = lsum[mf][1];
            }
        }
    }
}

// ---------------------------------------------------------------------------
// Combine split partials: (n0+n1)/(l0+l1) -> bf16 hi/lo token-major planes.
// ---------------------------------------------------------------------------
__global__ void __launch_bounds__(256)
combine_kernel()
{
    int idx = blockIdx.x * blockDim.x + threadIdx.x;
    const int total = SFR * HEADS * PTOK * (HD / 4);
    if (idx >= total) return;
    int c4 = idx & 15;
    int shp = idx >> 4;
    size_t row0 = shp;
    size_t row1 = (size_t)SFR * HEADS * PTOK + shp;
    float4 a = ((const float4*)(g_pacc + row0 * HD))[c4];
    float4 b = ((const float4*)(g_pacc + row1 * HD))[c4];
    float inv = 1.f / (g_pl[row0] + g_pl[row1]);
    float f0 = (a.x + b.x) * inv;
    float f1 = (a.y + b.y) * inv;
    float f2 = (a.z + b.z) * inv;
    float f3 = (a.w + b.w) * inv;
    int p = shp % PTOK;
    int sh = shp / PTOK;
    int hh = sh % HEADS;
    int ss = sh / HEADS;
    size_t base = (size_t)(ss * PTOK + p) * CDIM + hh * HD + c4 * 4;
    uint32_t h01 = pack_bf16(f0, f1);
    uint32_t h23 = pack_bf16(f2, f3);
    __nv_bfloat162 hv01 = *(__nv_bfloat162*)&h01;
    __nv_bfloat162 hv23 = *(__nv_bfloat162*)&h23;
    uint32_t l01 = pack_bf16(f0 - __bfloat162float(hv01.x),
                             f1 - __bfloat162float(hv01.y));
    uint32_t l23 = pack_bf16(f2 - __bfloat162float(hv23.x),
                             f3 - __bfloat162float(hv23.y));
    *(uint32_t*)&g_ahi[base] = h01;
    *(uint32_t*)&g_ahi[base + 2] = h23;
    *(uint32_t*)&g_alo[base] = l01;
    *(uint32_t*)&g_alo[base + 2] = l23;
}

// ---------------------------------------------------------------------------
extern "C" void kernel_launch(void* const* d_in, const int* in_sizes, int n_in,
                              void* d_out, int out_size)
{
    const float* x     = (const float*)d_in[0];
    const float* Wqkv  = (const float*)d_in[1];
    const float* bqkv  = (const float*)d_in[2];
    const float* qg    = (const float*)d_in[3];
    const float* qb    = (const float*)d_in[4];
    const float* kg    = (const float*)d_in[5];
    const float* kb    = (const float*)d_in[6];
    const float* Wproj = (const float*)d_in[7];
    const float* bproj = (const float*)d_in[8];
    const int*   gidx  = (const int*)d_in[9];
    const float* abias = (const float*)d_in[10];
    float* out = (float*)d_out;

    static int attr_set = 0;
    if (!attr_set) {
        cudaFuncSetAttribute(hmma_gemm_kernel<0>,
                             cudaFuncAttributeMaxDynamicSharedMemorySize, GEMM_SMEM);
        cudaFuncSetAttribute(hmma_gemm_kernel<1>,
                             cudaFuncAttributeMaxDynamicSharedMemorySize, GEMM_SMEM);
        cudaFuncSetAttribute(attn7_kernel,
                             cudaFuncAttributeMaxDynamicSharedMemorySize, AT_SMEM_BYTES);
        attr_set = 1;
    }

    const int n4 = NTOK * KDIM / 4;

    // 0) prep
    split_kernel<<<n4 / 256, 256>>>(x, n4);
    pad_kernel<<<(SFR * MKPAD + 255) / 256, 256>>>(gidx, abias);
    wsplit_kernel<0><<<dim3(NQKV / 32, KDIM / 32), 256>>>(Wqkv, NQKV);
    wsplit_kernel<1><<<dim3(1024 / 32, KDIM / 32), 256>>>(Wproj, 1024);

    // 1) QKV GEMM with FUSED LayerNorm + split epilogue -> g_{q,k,v}{hi,lo}
    hmma_gemm_kernel<0><<<dim3(NQKV / 128, NTOK / 128), 256, GEMM_SMEM>>>(
        bqkv, nullptr, NQKV, qg, qb, kg, kb);

    // 2) HMMA flash attention, KV-split x2 -> fp32 partials
    attn7_kernel<<<dim3(SFR, HEADS, NSPL), 224, AT_SMEM_BYTES>>>();

    // 2b) combine partials -> g_ahi/g_alo
    {
        const int total = SFR * HEADS * PTOK * (HD / 4);
        combine_kernel<<<(total + 255) / 256, 256>>>();
    }

    // 3) proj GEMM -> d_out
    hmma_gemm_kernel<1><<<dim3(1024 / 128, NTOK / 128), 256, GEMM_SMEM>>>(
        bproj, out, 1024, nullptr, nullptr, nullptr, nullptr);
}

// round 14
// speedup vs baseline: 1.3760x; 1.2624x over previous
#include <cuda_runtime.h>
#include <cuda_bf16.h>
#include <cuda_fp16.h>
#include <cstdint>

#define NTOK 6272
#define CDIM 1024
#define HEADS 16
#define HD 64
#define SFR 32
#define PTOK 196
#define MKV 1960
#define KT 32
#define MKPAD 1984
#define NSPL 2
#define NT_S 31
#define KVSPL (NT_S * KT)

#define KDIM 1024
#define NQKV 3072

// Scratch (no allocations anywhere)
__device__ __nv_bfloat16 g_ahi[(size_t)NTOK * KDIM];
__device__ __nv_bfloat16 g_alo[(size_t)NTOK * KDIM];
__device__ __nv_bfloat16 g_wqhi[(size_t)NQKV * KDIM];
__device__ __nv_bfloat16 g_wqlo[(size_t)NQKV * KDIM];
__device__ __nv_bfloat16 g_wphi[(size_t)1024 * KDIM];
__device__ __nv_bfloat16 g_wplo[(size_t)1024 * KDIM];
__device__ __half g_q16[(size_t)HEADS * NTOK * HD];
__device__ __half g_k16[(size_t)HEADS * NTOK * HD];
__device__ __half g_v16[(size_t)HEADS * NTOK * HD];
__device__ int   g_gidx2[SFR * MKPAD];
__device__ float g_bias2[SFR * MKPAD];
__device__ float g_pacc[(size_t)NSPL * SFR * HEADS * PTOK * HD];
__device__ float g_pl[NSPL * SFR * HEADS * PTOK];

// ---------------------------------------------------------------------------
// helpers
// ---------------------------------------------------------------------------
__device__ __forceinline__ uint32_t smem_u32(const void* p) {
    uint32_t a;
    asm("{ .reg .u64 t; cvta.to.shared.u64 t, %1; cvt.u32.u64 %0, t; }"
        : "=r"(a) : "l"(p));
    return a;
}
__device__ __forceinline__ void ldsm4(uint32_t addr, uint32_t& r0, uint32_t& r1,
                                      uint32_t& r2, uint32_t& r3) {
    asm volatile("ldmatrix.sync.aligned.m8n8.x4.shared.b16 {%0,%1,%2,%3}, [%4];"
                 : "=r"(r0), "=r"(r1), "=r"(r2), "=r"(r3) : "r"(addr));
}
__device__ __forceinline__ void ldsm4t(uint32_t addr, uint32_t& r0, uint32_t& r1,
                                       uint32_t& r2, uint32_t& r3) {
    asm volatile("ldmatrix.sync.aligned.m8n8.x4.trans.shared.b16 {%0,%1,%2,%3}, [%4];"
                 : "=r"(r0), "=r"(r1), "=r"(r2), "=r"(r3) : "r"(addr));
}
__device__ __forceinline__ void mma_bf16(float& d0, float& d1, float& d2, float& d3,
                                         uint32_t a0, uint32_t a1, uint32_t a2, uint32_t a3,
                                         uint32_t b0, uint32_t b1) {
    asm volatile(
        "mma.sync.aligned.m16n8k16.row.col.f32.bf16.bf16.f32 "
        "{%0,%1,%2,%3}, {%4,%5,%6,%7}, {%8,%9}, {%0,%1,%2,%3};"
        : "+f"(d0), "+f"(d1), "+f"(d2), "+f"(d3)
        : "r"(a0), "r"(a1), "r"(a2), "r"(a3), "r"(b0), "r"(b1));
}
__device__ __forceinline__ void mma_f16(float& d0, float& d1, float& d2, float& d3,
                                        uint32_t a0, uint32_t a1, uint32_t a2, uint32_t a3,
                                        uint32_t b0, uint32_t b1) {
    asm volatile(
        "mma.sync.aligned.m16n8k16.row.col.f32.f16.f16.f32 "
        "{%0,%1,%2,%3}, {%4,%5,%6,%7}, {%8,%9}, {%0,%1,%2,%3};"
        : "+f"(d0), "+f"(d1), "+f"(d2), "+f"(d3)
        : "r"(a0), "r"(a1), "r"(a2), "r"(a3), "r"(b0), "r"(b1));
}
__device__ __forceinline__ uint32_t pack_bf16(float a, float b) {
    __nv_bfloat162 t;
    t.x = __float2bfloat16_rn(a);
    t.y = __float2bfloat16_rn(b);
    return *(uint32_t*)&t;
}
__device__ __forceinline__ uint32_t pack_h16(float a, float b) {
    __half2 t = __floats2half2_rn(a, b);
    return *(uint32_t*)&t;
}
__device__ __forceinline__ void cpa16(uint32_t dst, const void* src) {
    asm volatile("cp.async.cg.shared.global [%0], [%1], 16;"
                 :: "r"(dst), "l"(src) : "memory");
}
__device__ __forceinline__ void cpa_commit() {
    asm volatile("cp.async.commit_group;" ::: "memory");
}
__device__ __forceinline__ void cpa_wait1() {
    asm volatile("cp.async.wait_group 1;" ::: "memory");
}

// ---------------------------------------------------------------------------
// Split fp32 -> bf16 hi/lo planes into g_ahi/g_alo (same layout)
// ---------------------------------------------------------------------------
__global__ void __launch_bounds__(256)
split_kernel(const float* __restrict__ src, int n4)
{
    int i = blockIdx.x * blockDim.x + threadIdx.x;
    if (i >= n4) return;
    float4 a = ((const float4*)src)[i];
    __nv_bfloat16 h0 = __float2bfloat16_rn(a.x);
    __nv_bfloat16 h1 = __float2bfloat16_rn(a.y);
    __nv_bfloat16 h2 = __float2bfloat16_rn(a.z);
    __nv_bfloat16 h3 = __float2bfloat16_rn(a.w);
    __nv_bfloat16 l0 = __float2bfloat16_rn(a.x - __bfloat162float(h0));
    __nv_bfloat16 l1 = __float2bfloat16_rn(a.y - __bfloat162float(h1));
    __nv_bfloat16 l2 = __float2bfloat16_rn(a.z - __bfloat162float(h2));
    __nv_bfloat16 l3 = __float2bfloat16_rn(a.w - __bfloat162float(h3));
    __nv_bfloat162 hh0; hh0.x = h0; hh0.y = h1;
    __nv_bfloat162 hh1; hh1.x = h2; hh1.y = h3;
    __nv_bfloat162 ll0; ll0.x = l0; ll0.y = l1;
    __nv_bfloat162 ll1; ll1.x = l2; ll1.y = l3;
    ((__nv_bfloat162*)g_ahi)[i * 2]     = hh0;
    ((__nv_bfloat162*)g_ahi)[i * 2 + 1] = hh1;
    ((__nv_bfloat162*)g_alo)[i * 2]     = ll0;
    ((__nv_bfloat162*)g_alo)[i * 2 + 1] = ll1;
}

// ---------------------------------------------------------------------------
// Pad/clamp gather indices and fold the static-max shift into the bias.
// ---------------------------------------------------------------------------
__global__ void __launch_bounds__(256)
pad_kernel(const int* __restrict__ gidx, const float* __restrict__ abias)
{
    int i = blockIdx.x * blockDim.x + threadIdx.x;
    if (i >= SFR * MKPAD) return;
    int s = i / MKPAD, j = i - s * MKPAD;
    int jj = (j < MKV) ? j : 0;
    g_gidx2[i] = gidx[s * MKV + jj];
    g_bias2[i] = (j < MKV) ? (abias[s * MKV + j] - 10.f) : -1e9f;
}

// ---------------------------------------------------------------------------
// Transpose + split: W [1024][N] fp32 -> hi/lo [N][1024] bf16
// ---------------------------------------------------------------------------
template <int WHICH>
__global__ void __launch_bounds__(256)
wsplit_kernel(const float* __restrict__ W, int N)
{
    __nv_bfloat16* hi = (WHICH == 0) ? g_wqhi : g_wphi;
    __nv_bfloat16* lo = (WHICH == 0) ? g_wqlo : g_wplo;
    __shared__ float t[32][33];
    int n0 = blockIdx.x * 32, k0 = blockIdx.y * 32;
    int tx = threadIdx.x & 31, ty = threadIdx.x >> 5;
#pragma unroll
    for (int r = 0; r < 4; r++)
        t[ty + r * 8][tx] = W[(size_t)(k0 + ty + r * 8) * N + n0 + tx];
    __syncthreads();
#pragma unroll
    for (int r = 0; r < 4; r++) {
        int n = ty + r * 8;
        float a = t[tx][n];
        __nv_bfloat16 h = __float2bfloat16_rn(a);
        __nv_bfloat16 l = __float2bfloat16_rn(a - __bfloat162float(h));
        size_t o = (size_t)(n0 + n) * KDIM + k0 + tx;
        hi[o] = h;
        lo[o] = l;
    }
}

// ---------------------------------------------------------------------------
// HMMA GEMM (R7-exact mainloop). MODE 0: fused LayerNorm + fp16 epilogue
// writing g_{q,k,v}16 planes. MODE 1: row-major C(+bias) -> Cout.
// ---------------------------------------------------------------------------
#define RSTR 24
#define TILE_E (128 * RSTR)
#define STAGE_E (4 * TILE_E)
#define STAGE_B (STAGE_E * 2)          // 24576 bytes
#define NSTAGE 3
#define GEMM_SMEM (NSTAGE * STAGE_B)   // 73728 bytes (>= 128*130*4 = 66560)
#define OFF_AH 0
#define OFF_AL TILE_E
#define OFF_BH (2 * TILE_E)
#define OFF_BL (3 * TILE_E)
#define LN_SS 130

template <int MODE>
__global__ void __launch_bounds__(256, 2)
hmma_gemm_kernel(const float* __restrict__ bias, float* __restrict__ Cout, int Nc,
                 const float* __restrict__ qg, const float* __restrict__ qb,
                 const float* __restrict__ kg, const float* __restrict__ kb)
{
    extern __shared__ __nv_bfloat16 smb[];
    const uint32_t su = smem_u32(smb);

    const __nv_bfloat16* Bhi = (MODE == 0) ? g_wqhi : g_wphi;
    const __nv_bfloat16* Blo = (MODE == 0) ? g_wqlo : g_wplo;

    const int tid = threadIdx.x;
    const int wid = tid >> 5;
    const int lane = tid & 31;
    const int wm = wid & 1;
    const int wn = wid >> 1;
    const int bm = blockIdx.y * 128;
    const int bn = blockIdx.x * 128;

    const int grow = tid >> 1;
    const int ghalf = tid & 1;
    const __nv_bfloat16* pAhi = g_ahi + (size_t)(bm + grow) * KDIM + ghalf * 8;
    const __nv_bfloat16* pAlo = g_alo + (size_t)(bm + grow) * KDIM + ghalf * 8;
    const __nv_bfloat16* pBhi = Bhi + (size_t)(bn + grow) * KDIM + ghalf * 8;
    const __nv_bfloat16* pBlo = Blo + (size_t)(bn + grow) * KDIM + ghalf * 8;
    const uint32_t sstore = (uint32_t)(grow * RSTR + ghalf * 8) * 2;

    const uint32_t aAddr = (uint32_t)((wm * 64 + (lane & 15)) * RSTR + (lane >> 4) * 8) * 2;
    const uint32_t bAddr = (uint32_t)((wn * 32 + (lane & 7) + ((lane >> 4) & 1) * 8) * RSTR
                                      + ((lane >> 3) & 1) * 8) * 2;

    float acc[4][4][4];
#pragma unroll
    for (int mf = 0; mf < 4; mf++)
#pragma unroll
        for (int nf = 0; nf < 4; nf++)
#pragma unroll
            for (int e = 0; e < 4; e++) acc[mf][nf][e] = 0.f;

    const int NCHUNK = KDIM / 16;      // 64

#pragma unroll
    for (int c = 0; c < 2; c++) {
        uint32_t sb = su + (uint32_t)c * STAGE_B + sstore;
        int ko = c * 16;
        cpa16(sb + OFF_AH * 2, pAhi + ko);
        cpa16(sb + OFF_AL * 2, pAlo + ko);
        cpa16(sb + OFF_BH * 2, pBhi + ko);
        cpa16(sb + OFF_BL * 2, pBlo + ko);
        cpa_commit();
    }

    for (int c = 0; c < NCHUNK; c++) {
        cpa_wait1();
        __syncthreads();

        if (c + 2 < NCHUNK) {
            int slot = (c + 2) % NSTAGE;
            uint32_t sb = su + (uint32_t)slot * STAGE_B + sstore;
            int ko = (c + 2) * 16;
            cpa16(sb + OFF_AH * 2, pAhi + ko);
            cpa16(sb + OFF_AL * 2, pAlo + ko);
            cpa16(sb + OFF_BH * 2, pBhi + ko);
            cpa16(sb + OFF_BL * 2, pBlo + ko);
        }
        cpa_commit();

        const uint32_t sb = su + (uint32_t)(c % NSTAGE) * STAGE_B;
        uint32_t bh[8], bl[8];
        ldsm4(sb + OFF_BH * 2 + bAddr, bh[0], bh[1], bh[2], bh[3]);
        ldsm4(sb + OFF_BH * 2 + bAddr + 16 * RSTR * 2, bh[4], bh[5], bh[6], bh[7]);
        ldsm4(sb + OFF_BL * 2 + bAddr, bl[0], bl[1], bl[2], bl[3]);
        ldsm4(sb + OFF_BL * 2 + bAddr + 16 * RSTR * 2, bl[4], bl[5], bl[6], bl[7]);

#pragma unroll
        for (int mf = 0; mf < 4; mf++) {
            uint32_t a0, a1, a2, a3;
            ldsm4(sb + OFF_AH * 2 + aAddr + mf * 16 * RSTR * 2, a0, a1, a2, a3);
#pragma unroll
            for (int nf = 0; nf < 4; nf++)
                mma_bf16(acc[mf][nf][0], acc[mf][nf][1], acc[mf][nf][2], acc[mf][nf][3],
                         a0, a1, a2, a3, bh[nf * 2], bh[nf * 2 + 1]);
#pragma unroll
            for (int nf = 0; nf < 4; nf++)
                mma_bf16(acc[mf][nf][0], acc[mf][nf][1], acc[mf][nf][2], acc[mf][nf][3],
                         a0, a1, a2, a3, bl[nf * 2], bl[nf * 2 + 1]);
            ldsm4(sb + OFF_AL * 2 + aAddr + mf * 16 * RSTR * 2, a0, a1, a2, a3);
#pragma unroll
            for (int nf = 0; nf < 4; nf++)
                mma_bf16(acc[mf][nf][0], acc[mf][nf][1], acc[mf][nf][2], acc[mf][nf][3],
                         a0, a1, a2, a3, bh[nf * 2], bh[nf * 2 + 1]);
        }
        __syncthreads();
    }

    if (MODE == 1) {
#pragma unroll
        for (int mf = 0; mf < 4; mf++) {
#pragma unroll
            for (int nf = 0; nf < 4; nf++) {
                int m0 = bm + wm * 64 + mf * 16 + (lane >> 2);
                int col = bn + wn * 32 + nf * 8 + (lane & 3) * 2;
                float2 bb = *(const float2*)&bias[col];
                float2 v0, v1;
                v0.x = acc[mf][nf][0] + bb.x;
                v0.y = acc[mf][nf][1] + bb.y;
                v1.x = acc[mf][nf][2] + bb.x;
                v1.y = acc[mf][nf][3] + bb.y;
                *(float2*)&Cout[(size_t)m0 * Nc + col] = v0;
                *(float2*)&Cout[(size_t)(m0 + 8) * Nc + col] = v1;
            }
        }
    } else {
        // ---- fused LayerNorm + fp16 epilogue ----
        float* S = (float*)smb;
#pragma unroll
        for (int mf = 0; mf < 4; mf++) {
#pragma unroll
            for (int nf = 0; nf < 4; nf++) {
                int ml = wm * 64 + mf * 16 + (lane >> 2);
                int cl = wn * 32 + nf * 8 + (lane & 3) * 2;
                float2 bb = *(const float2*)&bias[bn + cl];
                float2 v0, v1;
                v0.x = acc[mf][nf][0] + bb.x;
                v0.y = acc[mf][nf][1] + bb.y;
                v1.x = acc[mf][nf][2] + bb.x;
                v1.y = acc[mf][nf][3] + bb.y;
                *(float2*)&S[ml * LN_SS + cl] = v0;
                *(float2*)&S[(ml + 8) * LN_SS + cl] = v1;
            }
        }
        __syncthreads();

        const int row = tid & 127;
        const int hb = tid >> 7;
        const int gc = bn + hb * 64;
        const int part = gc >> 10;             // 0=q 1=k 2=v
        const int hh = (gc >> 6) & (HEADS - 1);
        const int m = bm + row;
        const float* Sr = &S[row * LN_SS + hb * 64];

        float sum = 0.f, sq = 0.f;
#pragma unroll
        for (int j = 0; j < 32; j++) {
            float2 t = *(const float2*)&Sr[j * 2];
            sum += t.x + t.y;
            sq += t.x * t.x + t.y * t.y;
        }
        float mu = 0.f, rstd = 1.f;
        const float* gp = (part == 0) ? qg : kg;
        const float* bp = (part == 0) ? qb : kb;
        if (part < 2) {
            mu = sum * (1.f / 64.f);
            float var = sq * (1.f / 64.f) - mu * mu;
            rstd = rsqrtf(var + 1e-6f);
        }
        __half* dst = (part == 0) ? g_q16 : (part == 1) ? g_k16 : g_v16;
        size_t obase = ((size_t)hh * NTOK + m) * HD;

#pragma unroll
        for (int jj = 0; jj < 8; jj++) {
            float v[8];
#pragma unroll
            for (int k = 0; k < 4; k++) {
                float2 t = *(const float2*)&Sr[jj * 8 + k * 2];
                v[k * 2] = t.x;
                v[k * 2 + 1] = t.y;
            }
            if (part < 2) {
#pragma unroll
                for (int k = 0; k < 8; k++)
                    v[k] = (v[k] - mu) * rstd * gp[jj * 8 + k] + bp[jj * 8 + k];
            }
            uint32_t w[4];
#pragma unroll
            for (int k = 0; k < 4; k++)
                w[k] = pack_h16(v[2 * k], v[2 * k + 1]);
            *(uint4*)&dst[obase + jj * 8] = *(uint4*)w;
        }
    }
}

// ---------------------------------------------------------------------------
// fp16 HMMA flash attention (attn9): single-product QK and PV.
// KV-split x2, register Q, register-prefetch gathered K/V tiles, 2 CTAs/SM.
// Epilogue stores UNNORMALIZED fp32 partials + row sums.
// ---------------------------------------------------------------------------
#define AST 72
#define KARR (KT * AST)                 // 2304 halves
#define BIAS_OFF (2 * KARR)             // halves
#define AT_SMEM_BYTES (BIAS_OFF * 2 + KT * 4 + 16)   // ~9.5 KB

__global__ void __launch_bounds__(224, 2)
attn9_kernel()
{
    extern __shared__ __half smh[];
    __half* Tile = smh;                 // [k16|v16][32][72]
    float* Bs = (float*)(smh + BIAS_OFF);
    const uint32_t su = smem_u32(smh);

    const int s = blockIdx.x, h = blockIdx.y, split = blockIdx.z;
    const int tid = threadIdx.x, wid = tid >> 5, lane = tid & 31;
    const int m0 = wid * 32;

    const __half* q16 = g_q16 + ((size_t)h * NTOK + (size_t)s * PTOK) * HD;
    const __half* k16 = g_k16 + (size_t)h * NTOK * HD;
    const __half* v16 = g_v16 + (size_t)h * NTOK * HD;

    // Q fragments in registers (fp16 A-frag layout, clamp rows >= 196)
    uint32_t qf[2][4][4];
    {
        int r = lane >> 2, c2 = (lane & 3) * 2;
#pragma unroll
        for (int mf = 0; mf < 2; mf++) {
            int r0 = m0 + mf * 16 + r;
            int r1 = r0 + 8;
            if (r0 > PTOK - 1) r0 = PTOK - 1;
            if (r1 > PTOK - 1) r1 = PTOK - 1;
#pragma unroll
            for (int kf = 0; kf < 4; kf++) {
                int c0 = kf * 16 + c2;
                qf[mf][kf][0] = *(const uint32_t*)(q16 + (size_t)r0 * HD + c0);
                qf[mf][kf][1] = *(const uint32_t*)(q16 + (size_t)r1 * HD + c0);
                qf[mf][kf][2] = *(const uint32_t*)(q16 + (size_t)r0 * HD + c0 + 8);
                qf[mf][kf][3] = *(const uint32_t*)(q16 + (size_t)r1 * HD + c0 + 8);
            }
        }
    }

    float o[2][8][4];
    float lsum[2][2];
#pragma unroll
    for (int mf = 0; mf < 2; mf++) {
        lsum[mf][0] = 0.f; lsum[mf][1] = 0.f;
#pragma unroll
        for (int nf = 0; nf < 8; nf++)
#pragma unroll
            for (int e = 0; e < 4; e++) o[mf][nf][e] = 0.f;
    }

    const int pbase = s * MKPAD + split * KVSPL;

    const uint32_t kaddr = su + 2 * (
        ((lane & 7) + ((lane >> 4) & 1) * 8) * AST + ((lane >> 3) & 1) * 8);
    const uint32_t vaddr = su + 2 * (KARR
        + ((lane & 7) + ((lane >> 3) & 1) * 8) * AST + ((lane >> 4) & 1) * 8);

    // prefetch tile 0: 2 arrays x 32 rows x 8 segs = 512 slots
    uint4 pf[3];
    float pbias = 0.f;
#pragma unroll
    for (int it = 0; it < 3; it++) {
        int slot = tid + it * 224;
        if (slot < 512) {
            int a = slot >> 8, r = (slot >> 3) & 31, seg = slot & 7;
            int tok = g_gidx2[pbase + r];
            const __half* bp = (a == 0) ? k16 : v16;
            pf[it] = *(const uint4*)(bp + (size_t)tok * HD + seg * 8);
        }
    }
    if (tid < KT) pbias = g_bias2[pbase + tid];

    for (int t = 0; t < NT_S; t++) {
        __syncthreads();
#pragma unroll
        for (int it = 0; it < 3; it++) {
            int slot = tid + it * 224;
            if (slot < 512) {
                int a = slot >> 8, r = (slot >> 3) & 31, seg = slot & 7;
                *(uint4*)&Tile[a * KARR + r * AST + seg * 8] = pf[it];
            }
        }
        if (tid < KT) Bs[tid] = pbias;
        __syncthreads();

        if (t + 1 < NT_S) {
            int ib = pbase + (t + 1) * KT;
#pragma unroll
            for (int it = 0; it < 3; it++) {
                int slot = tid + it * 224;
                if (slot < 512) {
                    int a = slot >> 8, r = (slot >> 3) & 31, seg = slot & 7;
                    int tok = g_gidx2[ib + r];
                    const __half* bp = (a == 0) ? k16 : v16;
                    pf[it] = *(const uint4*)(bp + (size_t)tok * HD + seg * 8);
                }
            }
            if (tid < KT) pbias = g_bias2[ib + tid];
        }

        // ---- QK: fp16 single product ----
        float sc[2][4][4];
#pragma unroll
        for (int mf = 0; mf < 2; mf++)
#pragma unroll
            for (int nf = 0; nf < 4; nf++)
#pragma unroll
                for (int e = 0; e < 4; e++) sc[mf][nf][e] = 0.f;

#pragma unroll
        for (int kf = 0; kf < 4; kf++) {
            uint32_t bh0[4], bh1[4];
            ldsm4(kaddr + kf * 32, bh0[0], bh0[1], bh0[2], bh0[3]);
            ldsm4(kaddr + kf * 32 + 16 * AST * 2, bh1[0], bh1[1], bh1[2], bh1[3]);
#pragma unroll
            for (int mf = 0; mf < 2; mf++) {
                uint32_t q0 = qf[mf][kf][0], q1 = qf[mf][kf][1];
                uint32_t q2 = qf[mf][kf][2], q3 = qf[mf][kf][3];
                mma_f16(sc[mf][0][0], sc[mf][0][1], sc[mf][0][2], sc[mf][0][3],
                        q0, q1, q2, q3, bh0[0], bh0[1]);
                mma_f16(sc[mf][1][0], sc[mf][1][1], sc[mf][1][2], sc[mf][1][3],
                        q0, q1, q2, q3, bh0[2], bh0[3]);
                mma_f16(sc[mf][2][0], sc[mf][2][1], sc[mf][2][2], sc[mf][2][3],
                        q0, q1, q2, q3, bh1[0], bh1[1]);
                mma_f16(sc[mf][3][0], sc[mf][3][1], sc[mf][3][2], sc[mf][3][3],
                        q0, q1, q2, q3, bh1[2], bh1[3]);
            }
        }

        // ---- softmax weights, packed to fp16 ----
        uint32_t phi[2][2][4];
#pragma unroll
        for (int mf = 0; mf < 2; mf++) {
#pragma unroll
            for (int nf = 0; nf < 4; nf++) {
                float2 bb = *(const float2*)&Bs[nf * 8 + (lane & 3) * 2];
                float p0 = __expf(fmaf(sc[mf][nf][0], 0.125f, bb.x));
                float p1 = __expf(fmaf(sc[mf][nf][1], 0.125f, bb.y));
                float p2 = __expf(fmaf(sc[mf][nf][2], 0.125f, bb.x));
                float p3 = __expf(fmaf(sc[mf][nf][3], 0.125f, bb.y));
                lsum[mf][0] += p0 + p1;
                lsum[mf][1] += p2 + p3;
                int kf2 = nf >> 1, hf = (nf & 1) * 2;
                phi[mf][kf2][hf] = pack_h16(p0, p1);
                phi[mf][kf2][hf + 1] = pack_h16(p2, p3);
            }
        }

        // ---- PV: fp16 single product, V via ldsm.trans ----
#pragma unroll
        for (int kf = 0; kf < 2; kf++) {
            uint32_t vhf[16];
#pragma unroll
            for (int db = 0; db < 4; db++) {
                ldsm4t(vaddr + kf * (16 * AST * 2) + db * 32,
                       vhf[db * 4], vhf[db * 4 + 1], vhf[db * 4 + 2], vhf[db * 4 + 3]);
            }
#pragma unroll
            for (int mf = 0; mf < 2; mf++) {
#pragma unroll
                for (int nfd = 0; nfd < 8; nfd++) {
                    int vi = (nfd >> 1) * 4 + (nfd & 1) * 2;
                    mma_f16(o[mf][nfd][0], o[mf][nfd][1], o[mf][nfd][2], o[mf][nfd][3],
                            phi[mf][kf][0], phi[mf][kf][1], phi[mf][kf][2], phi[mf][kf][3],
                            vhf[vi], vhf[vi + 1]);
                }
            }
        }
    }

    // reduce l over the 4 lanes sharing each row
#pragma unroll
    for (int mf = 0; mf < 2; mf++) {
#pragma unroll
        for (int j = 0; j < 2; j++) {
            float v = lsum[mf][j];
            v += __shfl_xor_sync(0xffffffffu, v, 1);
            v += __shfl_xor_sync(0xffffffffu, v, 2);
            lsum[mf][j] = v;
        }
    }

    // epilogue: store UNNORMALIZED partials (fp32) + row sums
    {
        int r = lane >> 2, c2 = (lane & 3) * 2;
        const size_t rrbase = ((size_t)(split * SFR + s) * HEADS + h) * PTOK;
#pragma unroll
        for (int mf = 0; mf < 2; mf++) {
            int rowq0 = m0 + mf * 16 + r;
            int rowq1 = rowq0 + 8;
            if (rowq0 < PTOK) {
                float* dst = g_pacc + (rrbase + rowq0) * HD + c2;
#pragma unroll
                for (int nfd = 0; nfd < 8; nfd++) {
                    float2 v; v.x = o[mf][nfd][0]; v.y = o[mf][nfd][1];
                    *(float2*)(dst + nfd * 8) = v;
                }
                if ((lane & 3) == 0) g_pl[rrbase + rowq0] = lsum[mf][0];
            }
            if (rowq1 < PTOK) {
                float* dst = g_pacc + (rrbase + rowq1) * HD + c2;
#pragma unroll
                for (int nfd = 0; nfd < 8; nfd++) {
                    float2 v; v.x = o[mf][nfd][2]; v.y = o[mf][nfd][3];
                    *(float2*)(dst + nfd * 8) = v;
                }
                if ((lane & 3) == 0) g_pl[rrbase + rowq1] = lsum[mf][1];
            }
        }
    }
}

// ---------------------------------------------------------------------------
// Combine split partials: (n0+n1)/(l0+l1) -> bf16 hi/lo token-major planes.
// ---------------------------------------------------------------------------
__global__ void __launch_bounds__(256)
combine_kernel()
{
    int idx = blockIdx.x * blockDim.x + threadIdx.x;
    const int total = SFR * HEADS * PTOK * (HD / 4);
    if (idx >= total) return;
    int c4 = idx & 15;
    int shp = idx >> 4;
    size_t row0 = shp;
    size_t row1 = (size_t)SFR * HEADS * PTOK + shp;
    float4 a = ((const float4*)(g_pacc + row0 * HD))[c4];
    float4 b = ((const float4*)(g_pacc + row1 * HD))[c4];
    float inv = 1.f / (g_pl[row0] + g_pl[row1]);
    float f0 = (a.x + b.x) * inv;
    float f1 = (a.y + b.y) * inv;
    float f2 = (a.z + b.z) * inv;
    float f3 = (a.w + b.w) * inv;
    int p = shp % PTOK;
    int sh = shp / PTOK;
    int hh = sh % HEADS;
    int ss = sh / HEADS;
    size_t base = (size_t)(ss * PTOK + p) * CDIM + hh * HD + c4 * 4;
    uint32_t h01 = pack_bf16(f0, f1);
    uint32_t h23 = pack_bf16(f2, f3);
    __nv_bfloat162 hv01 = *(__nv_bfloat162*)&h01;
    __nv_bfloat162 hv23 = *(__nv_bfloat162*)&h23;
    uint32_t l01 = pack_bf16(f0 - __bfloat162float(hv01.x),
                             f1 - __bfloat162float(hv01.y));
    uint32_t l23 = pack_bf16(f2 - __bfloat162float(hv23.x),
                             f3 - __bfloat162float(hv23.y));
    *(uint32_t*)&g_ahi[base] = h01;
    *(uint32_t*)&g_ahi[base + 2] = h23;
    *(uint32_t*)&g_alo[base] = l01;
    *(uint32_t*)&g_alo[base + 2] = l23;
}

// ---------------------------------------------------------------------------
extern "C" void kernel_launch(void* const* d_in, const int* in_sizes, int n_in,
                              void* d_out, int out_size)
{
    const float* x     = (const float*)d_in[0];
    const float* Wqkv  = (const float*)d_in[1];
    const float* bqkv  = (const float*)d_in[2];
    const float* qg    = (const float*)d_in[3];
    const float* qb    = (const float*)d_in[4];
    const float* kg    = (const float*)d_in[5];
    const float* kb    = (const float*)d_in[6];
    const float* Wproj = (const float*)d_in[7];
    const float* bproj = (const float*)d_in[8];
    const int*   gidx  = (const int*)d_in[9];
    const float* abias = (const float*)d_in[10];
    float* out = (float*)d_out;

    static int attr_set = 0;
    if (!attr_set) {
        cudaFuncSetAttribute(hmma_gemm_kernel<0>,
                             cudaFuncAttributeMaxDynamicSharedMemorySize, GEMM_SMEM);
        cudaFuncSetAttribute(hmma_gemm_kernel<1>,
                             cudaFuncAttributeMaxDynamicSharedMemorySize, GEMM_SMEM);
        cudaFuncSetAttribute(attn9_kernel,
                             cudaFuncAttributeMaxDynamicSharedMemorySize, AT_SMEM_BYTES);
        attr_set = 1;
    }

    const int n4 = NTOK * KDIM / 4;

    // 0) prep
    split_kernel<<<n4 / 256, 256>>>(x, n4);
    pad_kernel<<<(SFR * MKPAD + 255) / 256, 256>>>(gidx, abias);
    wsplit_kernel<0><<<dim3(NQKV / 32, KDIM / 32), 256>>>(Wqkv, NQKV);
    wsplit_kernel<1><<<dim3(1024 / 32, KDIM / 32), 256>>>(Wproj, 1024);

    // 1) QKV GEMM with FUSED LayerNorm + fp16 epilogue -> g_{q,k,v}16
    hmma_gemm_kernel<0><<<dim3(NQKV / 128, NTOK / 128), 256, GEMM_SMEM>>>(
        bqkv, nullptr, NQKV, qg, qb, kg, kb);

    // 2) fp16 flash attention, KV-split x2, 2 CTAs/SM -> fp32 partials
    attn9_kernel<<<dim3(SFR, HEADS, NSPL), 224, AT_SMEM_BYTES>>>();

    // 2b) combine partials -> g_ahi/g_alo
    {
        const int total = SFR * HEADS * PTOK * (HD / 4);
        combine_kernel<<<(total + 255) / 256, 256>>>();
    }

    // 3) proj GEMM -> d_out
    hmma_gemm_kernel<1><<<dim3(1024 / 128, NTOK / 128), 256, GEMM_SMEM>>>(
        bproj, out, 1024, nullptr, nullptr, nullptr, nullptr);
}

// round 15
// speedup vs baseline: 2.2106x; 1.6065x over previous
#include <cuda_runtime.h>
#include <cuda_bf16.h>
#include <cuda_fp16.h>
#include <cstdint>

#define NTOK 6272
#define CDIM 1024
#define HEADS 16
#define HD 64
#define SFR 32
#define PTOK 196
#define MKV 1960
#define KT 32
#define MKPAD 1984
#define NSPL 2
#define NT_S 31
#define KVSPL (NT_S * KT)

#define KDIM 1024
#define NQKV 3072

// Scratch (no allocations anywhere)
__device__ __half g_a16[(size_t)NTOK * KDIM];
__device__ __half g_wq16[(size_t)NQKV * KDIM];
__device__ __half g_wp16[(size_t)1024 * KDIM];
__device__ __half g_q16[(size_t)HEADS * NTOK * HD];
__device__ __half g_k16[(size_t)HEADS * NTOK * HD];
__device__ __half g_v16[(size_t)HEADS * NTOK * HD];
__device__ int   g_gidx2[SFR * MKPAD];
__device__ float g_bias2[SFR * MKPAD];
__device__ float g_pacc[(size_t)NSPL * SFR * HEADS * PTOK * HD];
__device__ float g_pl[NSPL * SFR * HEADS * PTOK];

// ---------------------------------------------------------------------------
// helpers
// ---------------------------------------------------------------------------
__device__ __forceinline__ uint32_t smem_u32(const void* p) {
    uint32_t a;
    asm("{ .reg .u64 t; cvta.to.shared.u64 t, %1; cvt.u32.u64 %0, t; }"
        : "=r"(a) : "l"(p));
    return a;
}
__device__ __forceinline__ void ldsm4(uint32_t addr, uint32_t& r0, uint32_t& r1,
                                      uint32_t& r2, uint32_t& r3) {
    asm volatile("ldmatrix.sync.aligned.m8n8.x4.shared.b16 {%0,%1,%2,%3}, [%4];"
                 : "=r"(r0), "=r"(r1), "=r"(r2), "=r"(r3) : "r"(addr));
}
__device__ __forceinline__ void ldsm4t(uint32_t addr, uint32_t& r0, uint32_t& r1,
                                       uint32_t& r2, uint32_t& r3) {
    asm volatile("ldmatrix.sync.aligned.m8n8.x4.trans.shared.b16 {%0,%1,%2,%3}, [%4];"
                 : "=r"(r0), "=r"(r1), "=r"(r2), "=r"(r3) : "r"(addr));
}
__device__ __forceinline__ void mma_f16(float& d0, float& d1, float& d2, float& d3,
                                        uint32_t a0, uint32_t a1, uint32_t a2, uint32_t a3,
                                        uint32_t b0, uint32_t b1) {
    asm volatile(
        "mma.sync.aligned.m16n8k16.row.col.f32.f16.f16.f32 "
        "{%0,%1,%2,%3}, {%4,%5,%6,%7}, {%8,%9}, {%0,%1,%2,%3};"
        : "+f"(d0), "+f"(d1), "+f"(d2), "+f"(d3)
        : "r"(a0), "r"(a1), "r"(a2), "r"(a3), "r"(b0), "r"(b1));
}
__device__ __forceinline__ uint32_t pack_h16(float a, float b) {
    __half2 t = __floats2half2_rn(a, b);
    return *(uint32_t*)&t;
}
__device__ __forceinline__ void cpa16(uint32_t dst, const void* src) {
    asm volatile("cp.async.cg.shared.global [%0], [%1], 16;"
                 :: "r"(dst), "l"(src) : "memory");
}
__device__ __forceinline__ void cpa_commit() {
    asm volatile("cp.async.commit_group;" ::: "memory");
}
__device__ __forceinline__ void cpa_wait1() {
    asm volatile("cp.async.wait_group 1;" ::: "memory");
}

// ---------------------------------------------------------------------------
// Convert fp32 -> fp16 plane into g_a16
// ---------------------------------------------------------------------------
__global__ void __launch_bounds__(256)
split_kernel(const float* __restrict__ src, int n4)
{
    int i = blockIdx.x * blockDim.x + threadIdx.x;
    if (i >= n4) return;
    float4 a = ((const float4*)src)[i];
    uint2 w;
    w.x = pack_h16(a.x, a.y);
    w.y = pack_h16(a.z, a.w);
    *(uint2*)&g_a16[(size_t)i * 4] = w;
}

// ---------------------------------------------------------------------------
// Pad/clamp gather indices and fold the static-max shift into the bias.
// ---------------------------------------------------------------------------
__global__ void __launch_bounds__(256)
pad_kernel(const int* __restrict__ gidx, const float* __restrict__ abias)
{
    int i = blockIdx.x * blockDim.x + threadIdx.x;
    if (i >= SFR * MKPAD) return;
    int s = i / MKPAD, j = i - s * MKPAD;
    int jj = (j < MKV) ? j : 0;
    g_gidx2[i] = gidx[s * MKV + jj];
    g_bias2[i] = (j < MKV) ? (abias[s * MKV + j] - 10.f) : -1e9f;
}

// ---------------------------------------------------------------------------
// Transpose + convert: W [1024][N] fp32 -> fp16 [N][1024]
// ---------------------------------------------------------------------------
template <int WHICH>
__global__ void __launch_bounds__(256)
wsplit_kernel(const float* __restrict__ W, int N)
{
    __half* dst = (WHICH == 0) ? g_wq16 : g_wp16;
    __shared__ float t[32][33];
    int n0 = blockIdx.x * 32, k0 = blockIdx.y * 32;
    int tx = threadIdx.x & 31, ty = threadIdx.x >> 5;
#pragma unroll
    for (int r = 0; r < 4; r++)
        t[ty + r * 8][tx] = W[(size_t)(k0 + ty + r * 8) * N + n0 + tx];
    __syncthreads();
#pragma unroll
    for (int r = 0; r < 4; r++) {
        int n = ty + r * 8;
        dst[(size_t)(n0 + n) * KDIM + k0 + tx] = __float2half_rn(t[tx][n]);
    }
}

// ---------------------------------------------------------------------------
// fp16 HMMA GEMM (R7 pipeline structure, single product).
// MODE 0: fused LayerNorm + fp16 epilogue -> g_{q,k,v}16.
// MODE 1: row-major C(+bias) -> Cout.
// ---------------------------------------------------------------------------
#define RSTR 24
#define TILE_E (128 * RSTR)            // halves per tile
#define STAGE_E (2 * TILE_E)           // A + B
#define STAGE_B (STAGE_E * 2)          // 12288 bytes
#define NSTAGE 3
#define PIPE_SMEM (NSTAGE * STAGE_B)   // 36864 bytes
#define LN_SS 130
#define GEMM_SMEM0 (128 * LN_SS * 4)   // 66560 (LN tile dominates)
#define GEMM_SMEM1 PIPE_SMEM
#define OFF_A 0
#define OFF_B TILE_E

template <int MODE>
__global__ void __launch_bounds__(256, 2)
hmma_gemm_kernel(const float* __restrict__ bias, float* __restrict__ Cout, int Nc,
                 const float* __restrict__ qg, const float* __restrict__ qb,
                 const float* __restrict__ kg, const float* __restrict__ kb)
{
    extern __shared__ __half smh0[];
    const uint32_t su = smem_u32(smh0);

    const __half* Bsrc = (MODE == 0) ? g_wq16 : g_wp16;

    const int tid = threadIdx.x;
    const int wid = tid >> 5;
    const int lane = tid & 31;
    const int wm = wid & 1;
    const int wn = wid >> 1;
    const int bm = blockIdx.y * 128;
    const int bn = blockIdx.x * 128;

    const int grow = tid >> 1;
    const int ghalf = tid & 1;
    const __half* pA = g_a16 + (size_t)(bm + grow) * KDIM + ghalf * 8;
    const __half* pB = Bsrc + (size_t)(bn + grow) * KDIM + ghalf * 8;
    const uint32_t sstore = (uint32_t)(grow * RSTR + ghalf * 8) * 2;

    const uint32_t aAddr = (uint32_t)((wm * 64 + (lane & 15)) * RSTR + (lane >> 4) * 8) * 2;
    const uint32_t bAddr = (uint32_t)((wn * 32 + (lane & 7) + ((lane >> 4) & 1) * 8) * RSTR
                                      + ((lane >> 3) & 1) * 8) * 2;

    float acc[4][4][4];
#pragma unroll
    for (int mf = 0; mf < 4; mf++)
#pragma unroll
        for (int nf = 0; nf < 4; nf++)
#pragma unroll
            for (int e = 0; e < 4; e++) acc[mf][nf][e] = 0.f;

    const int NCHUNK = KDIM / 16;      // 64

#pragma unroll
    for (int c = 0; c < 2; c++) {
        uint32_t sb = su + (uint32_t)c * STAGE_B + sstore;
        int ko = c * 16;
        cpa16(sb + OFF_A * 2, pA + ko);
        cpa16(sb + OFF_B * 2, pB + ko);
        cpa_commit();
    }

    for (int c = 0; c < NCHUNK; c++) {
        cpa_wait1();
        __syncthreads();

        if (c + 2 < NCHUNK) {
            int slot = (c + 2) % NSTAGE;
            uint32_t sb = su + (uint32_t)slot * STAGE_B + sstore;
            int ko = (c + 2) * 16;
            cpa16(sb + OFF_A * 2, pA + ko);
            cpa16(sb + OFF_B * 2, pB + ko);
        }
        cpa_commit();

        const uint32_t sb = su + (uint32_t)(c % NSTAGE) * STAGE_B;
        uint32_t bh[8];
        ldsm4(sb + OFF_B * 2 + bAddr, bh[0], bh[1], bh[2], bh[3]);
        ldsm4(sb + OFF_B * 2 + bAddr + 16 * RSTR * 2, bh[4], bh[5], bh[6], bh[7]);

#pragma unroll
        for (int mf = 0; mf < 4; mf++) {
            uint32_t a0, a1, a2, a3;
            ldsm4(sb + OFF_A * 2 + aAddr + mf * 16 * RSTR * 2, a0, a1, a2, a3);
#pragma unroll
            for (int nf = 0; nf < 4; nf++)
                mma_f16(acc[mf][nf][0], acc[mf][nf][1], acc[mf][nf][2], acc[mf][nf][3],
                        a0, a1, a2, a3, bh[nf * 2], bh[nf * 2 + 1]);
        }
        __syncthreads();
    }

    if (MODE == 1) {
#pragma unroll
        for (int mf = 0; mf < 4; mf++) {
#pragma unroll
            for (int nf = 0; nf < 4; nf++) {
                int m0 = bm + wm * 64 + mf * 16 + (lane >> 2);
                int col = bn + wn * 32 + nf * 8 + (lane & 3) * 2;
                float2 bb = *(const float2*)&bias[col];
                float2 v0, v1;
                v0.x = acc[mf][nf][0] + bb.x;
                v0.y = acc[mf][nf][1] + bb.y;
                v1.x = acc[mf][nf][2] + bb.x;
                v1.y = acc[mf][nf][3] + bb.y;
                *(float2*)&Cout[(size_t)m0 * Nc + col] = v0;
                *(float2*)&Cout[(size_t)(m0 + 8) * Nc + col] = v1;
            }
        }
    } else {
        // ---- fused LayerNorm + fp16 epilogue ----
        float* S = (float*)smh0;
#pragma unroll
        for (int mf = 0; mf < 4; mf++) {
#pragma unroll
            for (int nf = 0; nf < 4; nf++) {
                int ml = wm * 64 + mf * 16 + (lane >> 2);
                int cl = wn * 32 + nf * 8 + (lane & 3) * 2;
                float2 bb = *(const float2*)&bias[bn + cl];
                float2 v0, v1;
                v0.x = acc[mf][nf][0] + bb.x;
                v0.y = acc[mf][nf][1] + bb.y;
                v1.x = acc[mf][nf][2] + bb.x;
                v1.y = acc[mf][nf][3] + bb.y;
                *(float2*)&S[ml * LN_SS + cl] = v0;
                *(float2*)&S[(ml + 8) * LN_SS + cl] = v1;
            }
        }
        __syncthreads();

        const int row = tid & 127;
        const int hb = tid >> 7;
        const int gc = bn + hb * 64;
        const int part = gc >> 10;             // 0=q 1=k 2=v
        const int hh = (gc >> 6) & (HEADS - 1);
        const int m = bm + row;
        const float* Sr = &S[row * LN_SS + hb * 64];

        float sum = 0.f, sq = 0.f;
#pragma unroll
        for (int j = 0; j < 32; j++) {
            float2 t = *(const float2*)&Sr[j * 2];
            sum += t.x + t.y;
            sq += t.x * t.x + t.y * t.y;
        }
        float mu = 0.f, rstd = 1.f;
        const float* gp = (part == 0) ? qg : kg;
        const float* bp = (part == 0) ? qb : kb;
        if (part < 2) {
            mu = sum * (1.f / 64.f);
            float var = sq * (1.f / 64.f) - mu * mu;
            rstd = rsqrtf(var + 1e-6f);
        }
        __half* dst = (part == 0) ? g_q16 : (part == 1) ? g_k16 : g_v16;
        size_t obase = ((size_t)hh * NTOK + m) * HD;

#pragma unroll
        for (int jj = 0; jj < 8; jj++) {
            float v[8];
#pragma unroll
            for (int k = 0; k < 4; k++) {
                float2 t = *(const float2*)&Sr[jj * 8 + k * 2];
                v[k * 2] = t.x;
                v[k * 2 + 1] = t.y;
            }
            if (part < 2) {
#pragma unroll
                for (int k = 0; k < 8; k++)
                    v[k] = (v[k] - mu) * rstd * gp[jj * 8 + k] + bp[jj * 8 + k];
            }
            uint32_t w[4];
#pragma unroll
            for (int k = 0; k < 4; k++)
                w[k] = pack_h16(v[2 * k], v[2 * k + 1]);
            *(uint4*)&dst[obase + jj * 8] = *(uint4*)w;
        }
    }
}

// ---------------------------------------------------------------------------
// fp16 HMMA flash attention (attn9, R14-exact WIN version).
// ---------------------------------------------------------------------------
#define AST 72
#define KARR (KT * AST)
#define BIAS_OFF (2 * KARR)
#define AT_SMEM_BYTES (BIAS_OFF * 2 + KT * 4 + 16)

__global__ void __launch_bounds__(224, 2)
attn9_kernel()
{
    extern __shared__ __half smh[];
    __half* Tile = smh;
    float* Bs = (float*)(smh + BIAS_OFF);
    const uint32_t su = smem_u32(smh);

    const int s = blockIdx.x, h = blockIdx.y, split = blockIdx.z;
    const int tid = threadIdx.x, wid = tid >> 5, lane = tid & 31;
    const int m0 = wid * 32;

    const __half* q16 = g_q16 + ((size_t)h * NTOK + (size_t)s * PTOK) * HD;
    const __half* k16 = g_k16 + (size_t)h * NTOK * HD;
    const __half* v16 = g_v16 + (size_t)h * NTOK * HD;

    uint32_t qf[2][4][4];
    {
        int r = lane >> 2, c2 = (lane & 3) * 2;
#pragma unroll
        for (int mf = 0; mf < 2; mf++) {
            int r0 = m0 + mf * 16 + r;
            int r1 = r0 + 8;
            if (r0 > PTOK - 1) r0 = PTOK - 1;
            if (r1 > PTOK - 1) r1 = PTOK - 1;
#pragma unroll
            for (int kf = 0; kf < 4; kf++) {
                int c0 = kf * 16 + c2;
                qf[mf][kf][0] = *(const uint32_t*)(q16 + (size_t)r0 * HD + c0);
                qf[mf][kf][1] = *(const uint32_t*)(q16 + (size_t)r1 * HD + c0);
                qf[mf][kf][2] = *(const uint32_t*)(q16 + (size_t)r0 * HD + c0 + 8);
                qf[mf][kf][3] = *(const uint32_t*)(q16 + (size_t)r1 * HD + c0 + 8);
            }
        }
    }

    float o[2][8][4];
    float lsum[2][2];
#pragma unroll
    for (int mf = 0; mf < 2; mf++) {
        lsum[mf][0] = 0.f; lsum[mf][1] = 0.f;
#pragma unroll
        for (int nf = 0; nf < 8; nf++)
#pragma unroll
            for (int e = 0; e < 4; e++) o[mf][nf][e] = 0.f;
    }

    const int pbase = s * MKPAD + split * KVSPL;

    const uint32_t kaddr = su + 2 * (
        ((lane & 7) + ((lane >> 4) & 1) * 8) * AST + ((lane >> 3) & 1) * 8);
    const uint32_t vaddr = su + 2 * (KARR
        + ((lane & 7) + ((lane >> 3) & 1) * 8) * AST + ((lane >> 4) & 1) * 8);

    uint4 pf[3];
    float pbias = 0.f;
#pragma unroll
    for (int it = 0; it < 3; it++) {
        int slot = tid + it * 224;
        if (slot < 512) {
            int a = slot >> 8, r = (slot >> 3) & 31, seg = slot & 7;
            int tok = g_gidx2[pbase + r];
            const __half* bp = (a == 0) ? k16 : v16;
            pf[it] = *(const uint4*)(bp + (size_t)tok * HD + seg * 8);
        }
    }
    if (tid < KT) pbias = g_bias2[pbase + tid];

    for (int t = 0; t < NT_S; t++) {
        __syncthreads();
#pragma unroll
        for (int it = 0; it < 3; it++) {
            int slot = tid + it * 224;
            if (slot < 512) {
                int a = slot >> 8, r = (slot >> 3) & 31, seg = slot & 7;
                *(uint4*)&Tile[a * KARR + r * AST + seg * 8] = pf[it];
            }
        }
        if (tid < KT) Bs[tid] = pbias;
        __syncthreads();

        if (t + 1 < NT_S) {
            int ib = pbase + (t + 1) * KT;
#pragma unroll
            for (int it = 0; it < 3; it++) {
                int slot = tid + it * 224;
                if (slot < 512) {
                    int a = slot >> 8, r = (slot >> 3) & 31, seg = slot & 7;
                    int tok = g_gidx2[ib + r];
                    const __half* bp = (a == 0) ? k16 : v16;
                    pf[it] = *(const uint4*)(bp + (size_t)tok * HD + seg * 8);
                }
            }
            if (tid < KT) pbias = g_bias2[ib + tid];
        }

        // ---- QK: fp16 single product ----
        float sc[2][4][4];
#pragma unroll
        for (int mf = 0; mf < 2; mf++)
#pragma unroll
            for (int nf = 0; nf < 4; nf++)
#pragma unroll
                for (int e = 0; e < 4; e++) sc[mf][nf][e] = 0.f;

#pragma unroll
        for (int kf = 0; kf < 4; kf++) {
            uint32_t bh0[4], bh1[4];
            ldsm4(kaddr + kf * 32, bh0[0], bh0[1], bh0[2], bh0[3]);
            ldsm4(kaddr + kf * 32 + 16 * AST * 2, bh1[0], bh1[1], bh1[2], bh1[3]);
#pragma unroll
            for (int mf = 0; mf < 2; mf++) {
                uint32_t q0 = qf[mf][kf][0], q1 = qf[mf][kf][1];
                uint32_t q2 = qf[mf][kf][2], q3 = qf[mf][kf][3];
                mma_f16(sc[mf][0][0], sc[mf][0][1], sc[mf][0][2], sc[mf][0][3],
                        q0, q1, q2, q3, bh0[0], bh0[1]);
                mma_f16(sc[mf][1][0], sc[mf][1][1], sc[mf][1][2], sc[mf][1][3],
                        q0, q1, q2, q3, bh0[2], bh0[3]);
                mma_f16(sc[mf][2][0], sc[mf][2][1], sc[mf][2][2], sc[mf][2][3],
                        q0, q1, q2, q3, bh1[0], bh1[1]);
                mma_f16(sc[mf][3][0], sc[mf][3][1], sc[mf][3][2], sc[mf][3][3],
                        q0, q1, q2, q3, bh1[2], bh1[3]);
            }
        }

        // ---- softmax weights, packed to fp16 ----
        uint32_t phi[2][2][4];
#pragma unroll
        for (int mf = 0; mf < 2; mf++) {
#pragma unroll
            for (int nf = 0; nf < 4; nf++) {
                float2 bb = *(const float2*)&Bs[nf * 8 + (lane & 3) * 2];
                float p0 = __expf(fmaf(sc[mf][nf][0], 0.125f, bb.x));
                float p1 = __expf(fmaf(sc[mf][nf][1], 0.125f, bb.y));
                float p2 = __expf(fmaf(sc[mf][nf][2], 0.125f, bb.x));
                float p3 = __expf(fmaf(sc[mf][nf][3], 0.125f, bb.y));
                lsum[mf][0] += p0 + p1;
                lsum[mf][1] += p2 + p3;
                int kf2 = nf >> 1, hf = (nf & 1) * 2;
                phi[mf][kf2][hf] = pack_h16(p0, p1);
                phi[mf][kf2][hf + 1] = pack_h16(p2, p3);
            }
        }

        // ---- PV: fp16 single product, V via ldsm.trans ----
#pragma unroll
        for (int kf = 0; kf < 2; kf++) {
            uint32_t vhf[16];
#pragma unroll
            for (int db = 0; db < 4; db++) {
                ldsm4t(vaddr + kf * (16 * AST * 2) + db * 32,
                       vhf[db * 4], vhf[db * 4 + 1], vhf[db * 4 + 2], vhf[db * 4 + 3]);
            }
#pragma unroll
            for (int mf = 0; mf < 2; mf++) {
#pragma unroll
                for (int nfd = 0; nfd < 8; nfd++) {
                    int vi = (nfd >> 1) * 4 + (nfd & 1) * 2;
                    mma_f16(o[mf][nfd][0], o[mf][nfd][1], o[mf][nfd][2], o[mf][nfd][3],
                            phi[mf][kf][0], phi[mf][kf][1], phi[mf][kf][2], phi[mf][kf][3],
                            vhf[vi], vhf[vi + 1]);
                }
            }
        }
    }

#pragma unroll
    for (int mf = 0; mf < 2; mf++) {
#pragma unroll
        for (int j = 0; j < 2; j++) {
            float v = lsum[mf][j];
            v += __shfl_xor_sync(0xffffffffu, v, 1);
            v += __shfl_xor_sync(0xffffffffu, v, 2);
            lsum[mf][j] = v;
        }
    }

    {
        int r = lane >> 2, c2 = (lane & 3) * 2;
        const size_t rrbase = ((size_t)(split * SFR + s) * HEADS + h) * PTOK;
#pragma unroll
        for (int mf = 0; mf < 2; mf++) {
            int rowq0 = m0 + mf * 16 + r;
            int rowq1 = rowq0 + 8;
            if (rowq0 < PTOK) {
                float* dst = g_pacc + (rrbase + rowq0) * HD + c2;
#pragma unroll
                for (int nfd = 0; nfd < 8; nfd++) {
                    float2 v; v.x = o[mf][nfd][0]; v.y = o[mf][nfd][1];
                    *(float2*)(dst + nfd * 8) = v;
                }
                if ((lane & 3) == 0) g_pl[rrbase + rowq0] = lsum[mf][0];
            }
            if (rowq1 < PTOK) {
                float* dst = g_pacc + (rrbase + rowq1) * HD + c2;
#pragma unroll
                for (int nfd = 0; nfd < 8; nfd++) {
                    float2 v; v.x = o[mf][nfd][2]; v.y = o[mf][nfd][3];
                    *(float2*)(dst + nfd * 8) = v;
                }
                if ((lane & 3) == 0) g_pl[rrbase + rowq1] = lsum[mf][1];
            }
        }
    }
}

// ---------------------------------------------------------------------------
// Combine split partials: (n0+n1)/(l0+l1) -> fp16 token-major plane g_a16.
// ---------------------------------------------------------------------------
__global__ void __launch_bounds__(256)
combine_kernel()
{
    int idx = blockIdx.x * blockDim.x + threadIdx.x;
    const int total = SFR * HEADS * PTOK * (HD / 4);
    if (idx >= total) return;
    int c4 = idx & 15;
    int shp = idx >> 4;
    size_t row0 = shp;
    size_t row1 = (size_t)SFR * HEADS * PTOK + shp;
    float4 a = ((const float4*)(g_pacc + row0 * HD))[c4];
    float4 b = ((const float4*)(g_pacc + row1 * HD))[c4];
    float inv = 1.f / (g_pl[row0] + g_pl[row1]);
    float f0 = (a.x + b.x) * inv;
    float f1 = (a.y + b.y) * inv;
    float f2 = (a.z + b.z) * inv;
    float f3 = (a.w + b.w) * inv;
    int p = shp % PTOK;
    int sh = shp / PTOK;
    int hh = sh % HEADS;
    int ss = sh / HEADS;
    size_t base = (size_t)(ss * PTOK + p) * CDIM + hh * HD + c4 * 4;
    uint2 w;
    w.x = pack_h16(f0, f1);
    w.y = pack_h16(f2, f3);
    *(uint2*)&g_a16[base] = w;
}

// ---------------------------------------------------------------------------
extern "C" void kernel_launch(void* const* d_in, const int* in_sizes, int n_in,
                              void* d_out, int out_size)
{
    const float* x     = (const float*)d_in[0];
    const float* Wqkv  = (const float*)d_in[1];
    const float* bqkv  = (const float*)d_in[2];
    const float* qg    = (const float*)d_in[3];
    const float* qb    = (const float*)d_in[4];
    const float* kg    = (const float*)d_in[5];
    const float* kb    = (const float*)d_in[6];
    const float* Wproj = (const float*)d_in[7];
    const float* bproj = (const float*)d_in[8];
    const int*   gidx  = (const int*)d_in[9];
    const float* abias = (const float*)d_in[10];
    float* out = (float*)d_out;

    static int attr_set = 0;
    if (!attr_set) {
        cudaFuncSetAttribute(hmma_gemm_kernel<0>,
                             cudaFuncAttributeMaxDynamicSharedMemorySize, GEMM_SMEM0);
        cudaFuncSetAttribute(hmma_gemm_kernel<1>,
                             cudaFuncAttributeMaxDynamicSharedMemorySize, GEMM_SMEM1);
        cudaFuncSetAttribute(attn9_kernel,
                             cudaFuncAttributeMaxDynamicSharedMemorySize, AT_SMEM_BYTES);
        attr_set = 1;
    }

    const int n4 = NTOK * KDIM / 4;

    // 0) prep
    split_kernel<<<n4 / 256, 256>>>(x, n4);
    pad_kernel<<<(SFR * MKPAD + 255) / 256, 256>>>(gidx, abias);
    wsplit_kernel<0><<<dim3(NQKV / 32, KDIM / 32), 256>>>(Wqkv, NQKV);
    wsplit_kernel<1><<<dim3(1024 / 32, KDIM / 32), 256>>>(Wproj, 1024);

    // 1) QKV GEMM (fp16) with FUSED LayerNorm + fp16 epilogue -> g_{q,k,v}16
    hmma_gemm_kernel<0><<<dim3(NQKV / 128, NTOK / 128), 256, GEMM_SMEM0>>>(
        bqkv, nullptr, NQKV, qg, qb, kg, kb);

    // 2) fp16 flash attention, KV-split x2, 2 CTAs/SM -> fp32 partials
    attn9_kernel<<<dim3(SFR, HEADS, NSPL), 224, AT_SMEM_BYTES>>>();

    // 2b) combine partials -> g_a16
    {
        const int total = SFR * HEADS * PTOK * (HD / 4);
        combine_kernel<<<(total + 255) / 256, 256>>>();
    }

    // 3) proj GEMM (fp16) -> d_out
    hmma_gemm_kernel<1><<<dim3(1024 / 128, NTOK / 128), 256, GEMM_SMEM1>>>(
        bproj, out, 1024, nullptr, nullptr, nullptr, nullptr);
}

// round 16
// speedup vs baseline: 2.4910x; 1.1269x over previous
#include <cuda_runtime.h>
#include <cuda_bf16.h>
#include <cuda_fp16.h>
#include <cstdint>

#define NTOK 6272
#define CDIM 1024
#define HEADS 16
#define HD 64
#define SFR 32
#define PTOK 196
#define MKV 1960
#define KT 32
#define MKPAD 1984
#define NSPL 2
#define NT_S 31
#define KVSPL (NT_S * KT)

#define KDIM 1024
#define NQKV 3072

// Scratch (no allocations anywhere)
__device__ __half g_a16[(size_t)NTOK * KDIM];
__device__ __half g_wq16[(size_t)NQKV * KDIM];
__device__ __half g_wp16[(size_t)1024 * KDIM];
__device__ __half g_q16[(size_t)HEADS * NTOK * HD];
__device__ __half g_k16[(size_t)HEADS * NTOK * HD];
__device__ __half g_v16[(size_t)HEADS * NTOK * HD];
__device__ int   g_gidx2[SFR * MKPAD];
__device__ float g_bias2[SFR * MKPAD];
__device__ int   g_nreal[SFR];
__device__ float g_pacc[(size_t)NSPL * SFR * HEADS * PTOK * HD];
__device__ float g_pl[NSPL * SFR * HEADS * PTOK];

// ---------------------------------------------------------------------------
// helpers
// ---------------------------------------------------------------------------
__device__ __forceinline__ uint32_t smem_u32(const void* p) {
    uint32_t a;
    asm("{ .reg .u64 t; cvta.to.shared.u64 t, %1; cvt.u32.u64 %0, t; }"
        : "=r"(a) : "l"(p));
    return a;
}
__device__ __forceinline__ void ldsm4(uint32_t addr, uint32_t& r0, uint32_t& r1,
                                      uint32_t& r2, uint32_t& r3) {
    asm volatile("ldmatrix.sync.aligned.m8n8.x4.shared.b16 {%0,%1,%2,%3}, [%4];"
                 : "=r"(r0), "=r"(r1), "=r"(r2), "=r"(r3) : "r"(addr));
}
__device__ __forceinline__ void ldsm4t(uint32_t addr, uint32_t& r0, uint32_t& r1,
                                       uint32_t& r2, uint32_t& r3) {
    asm volatile("ldmatrix.sync.aligned.m8n8.x4.trans.shared.b16 {%0,%1,%2,%3}, [%4];"
                 : "=r"(r0), "=r"(r1), "=r"(r2), "=r"(r3) : "r"(addr));
}
__device__ __forceinline__ void mma_f16(float& d0, float& d1, float& d2, float& d3,
                                        uint32_t a0, uint32_t a1, uint32_t a2, uint32_t a3,
                                        uint32_t b0, uint32_t b1) {
    asm volatile(
        "mma.sync.aligned.m16n8k16.row.col.f32.f16.f16.f32 "
        "{%0,%1,%2,%3}, {%4,%5,%6,%7}, {%8,%9}, {%0,%1,%2,%3};"
        : "+f"(d0), "+f"(d1), "+f"(d2), "+f"(d3)
        : "r"(a0), "r"(a1), "r"(a2), "r"(a3), "r"(b0), "r"(b1));
}
__device__ __forceinline__ uint32_t pack_h16(float a, float b) {
    __half2 t = __floats2half2_rn(a, b);
    return *(uint32_t*)&t;
}
__device__ __forceinline__ void cpa16(uint32_t dst, const void* src) {
    asm volatile("cp.async.cg.shared.global [%0], [%1], 16;"
                 :: "r"(dst), "l"(src) : "memory");
}
__device__ __forceinline__ void cpa_commit() {
    asm volatile("cp.async.commit_group;" ::: "memory");
}
__device__ __forceinline__ void cpa_wait1() {
    asm volatile("cp.async.wait_group 1;" ::: "memory");
}

// ---------------------------------------------------------------------------
// Convert fp32 -> fp16 plane into g_a16
// ---------------------------------------------------------------------------
__global__ void __launch_bounds__(256)
split_kernel(const float* __restrict__ src, int n4)
{
    int i = blockIdx.x * blockDim.x + threadIdx.x;
    if (i >= n4) return;
    float4 a = ((const float4*)src)[i];
    uint2 w;
    w.x = pack_h16(a.x, a.y);
    w.y = pack_h16(a.z, a.w);
    *(uint2*)&g_a16[(size_t)i * 4] = w;
}

// ---------------------------------------------------------------------------
// Pad/clamp gather indices and fold the static-max shift into the bias.
// ---------------------------------------------------------------------------
__global__ void __launch_bounds__(256)
pad_kernel(const int* __restrict__ gidx, const float* __restrict__ abias)
{
    int i = blockIdx.x * blockDim.x + threadIdx.x;
    if (i >= SFR * MKPAD) return;
    int s = i / MKPAD, j = i - s * MKPAD;
    int jj = (j < MKV) ? j : 0;
    g_gidx2[i] = gidx[s * MKV + jj];
    g_bias2[i] = (j < MKV) ? (abias[s * MKV + j] - 10.f) : -1e9f;
}

// ---------------------------------------------------------------------------
// Count real (non-padded) keys per frame: bias > -1e8. One block per frame.
// ---------------------------------------------------------------------------
__global__ void __launch_bounds__(256)
count_kernel(const float* __restrict__ abias)
{
    __shared__ int red[8];
    int s = blockIdx.x;
    int tid = threadIdx.x;
    int cnt = 0;
    for (int j = tid; j < MKV; j += 256)
        cnt += (abias[s * MKV + j] > -1e8f) ? 1 : 0;
#pragma unroll
    for (int o = 16; o; o >>= 1) cnt += __shfl_xor_sync(0xffffffffu, cnt, o);
    if ((tid & 31) == 0) red[tid >> 5] = cnt;
    __syncthreads();
    if (tid == 0) {
        int t = 0;
#pragma unroll
        for (int w = 0; w < 8; w++) t += red[w];
        g_nreal[s] = t;
    }
}

// ---------------------------------------------------------------------------
// Transpose + convert: W [1024][N] fp32 -> fp16 [N][1024]
// ---------------------------------------------------------------------------
template <int WHICH>
__global__ void __launch_bounds__(256)
wsplit_kernel(const float* __restrict__ W, int N)
{
    __half* dst = (WHICH == 0) ? g_wq16 : g_wp16;
    __shared__ float t[32][33];
    int n0 = blockIdx.x * 32, k0 = blockIdx.y * 32;
    int tx = threadIdx.x & 31, ty = threadIdx.x >> 5;
#pragma unroll
    for (int r = 0; r < 4; r++)
        t[ty + r * 8][tx] = W[(size_t)(k0 + ty + r * 8) * N + n0 + tx];
    __syncthreads();
#pragma unroll
    for (int r = 0; r < 4; r++) {
        int n = ty + r * 8;
        dst[(size_t)(n0 + n) * KDIM + k0 + tx] = __float2half_rn(t[tx][n]);
    }
}

// ---------------------------------------------------------------------------
// fp16 HMMA GEMM (R15-exact WIN).
// MODE 0: fused LayerNorm + fp16 epilogue -> g_{q,k,v}16.
// MODE 1: row-major C(+bias) -> Cout.
// ---------------------------------------------------------------------------
#define RSTR 24
#define TILE_E (128 * RSTR)
#define STAGE_E (2 * TILE_E)
#define STAGE_B (STAGE_E * 2)          // 12288 bytes
#define NSTAGE 3
#define PIPE_SMEM (NSTAGE * STAGE_B)   // 36864 bytes
#define LN_SS 130
#define GEMM_SMEM0 (128 * LN_SS * 4)   // 66560
#define GEMM_SMEM1 PIPE_SMEM
#define OFF_A 0
#define OFF_B TILE_E

template <int MODE>
__global__ void __launch_bounds__(256, 2)
hmma_gemm_kernel(const float* __restrict__ bias, float* __restrict__ Cout, int Nc,
                 const float* __restrict__ qg, const float* __restrict__ qb,
                 const float* __restrict__ kg, const float* __restrict__ kb)
{
    extern __shared__ __half smh0[];
    const uint32_t su = smem_u32(smh0);

    const __half* Bsrc = (MODE == 0) ? g_wq16 : g_wp16;

    const int tid = threadIdx.x;
    const int wid = tid >> 5;
    const int lane = tid & 31;
    const int wm = wid & 1;
    const int wn = wid >> 1;
    const int bm = blockIdx.y * 128;
    const int bn = blockIdx.x * 128;

    const int grow = tid >> 1;
    const int ghalf = tid & 1;
    const __half* pA = g_a16 + (size_t)(bm + grow) * KDIM + ghalf * 8;
    const __half* pB = Bsrc + (size_t)(bn + grow) * KDIM + ghalf * 8;
    const uint32_t sstore = (uint32_t)(grow * RSTR + ghalf * 8) * 2;

    const uint32_t aAddr = (uint32_t)((wm * 64 + (lane & 15)) * RSTR + (lane >> 4) * 8) * 2;
    const uint32_t bAddr = (uint32_t)((wn * 32 + (lane & 7) + ((lane >> 4) & 1) * 8) * RSTR
                                      + ((lane >> 3) & 1) * 8) * 2;

    float acc[4][4][4];
#pragma unroll
    for (int mf = 0; mf < 4; mf++)
#pragma unroll
        for (int nf = 0; nf < 4; nf++)
#pragma unroll
            for (int e = 0; e < 4; e++) acc[mf][nf][e] = 0.f;

    const int NCHUNK = KDIM / 16;      // 64

#pragma unroll
    for (int c = 0; c < 2; c++) {
        uint32_t sb = su + (uint32_t)c * STAGE_B + sstore;
        int ko = c * 16;
        cpa16(sb + OFF_A * 2, pA + ko);
        cpa16(sb + OFF_B * 2, pB + ko);
        cpa_commit();
    }

    for (int c = 0; c < NCHUNK; c++) {
        cpa_wait1();
        __syncthreads();

        if (c + 2 < NCHUNK) {
            int slot = (c + 2) % NSTAGE;
            uint32_t sb = su + (uint32_t)slot * STAGE_B + sstore;
            int ko = (c + 2) * 16;
            cpa16(sb + OFF_A * 2, pA + ko);
            cpa16(sb + OFF_B * 2, pB + ko);
        }
        cpa_commit();

        const uint32_t sb = su + (uint32_t)(c % NSTAGE) * STAGE_B;
        uint32_t bh[8];
        ldsm4(sb + OFF_B * 2 + bAddr, bh[0], bh[1], bh[2], bh[3]);
        ldsm4(sb + OFF_B * 2 + bAddr + 16 * RSTR * 2, bh[4], bh[5], bh[6], bh[7]);

#pragma unroll
        for (int mf = 0; mf < 4; mf++) {
            uint32_t a0, a1, a2, a3;
            ldsm4(sb + OFF_A * 2 + aAddr + mf * 16 * RSTR * 2, a0, a1, a2, a3);
#pragma unroll
            for (int nf = 0; nf < 4; nf++)
                mma_f16(acc[mf][nf][0], acc[mf][nf][1], acc[mf][nf][2], acc[mf][nf][3],
                        a0, a1, a2, a3, bh[nf * 2], bh[nf * 2 + 1]);
        }
        __syncthreads();
    }

    if (MODE == 1) {
#pragma unroll
        for (int mf = 0; mf < 4; mf++) {
#pragma unroll
            for (int nf = 0; nf < 4; nf++) {
                int m0 = bm + wm * 64 + mf * 16 + (lane >> 2);
                int col = bn + wn * 32 + nf * 8 + (lane & 3) * 2;
                float2 bb = *(const float2*)&bias[col];
                float2 v0, v1;
                v0.x = acc[mf][nf][0] + bb.x;
                v0.y = acc[mf][nf][1] + bb.y;
                v1.x = acc[mf][nf][2] + bb.x;
                v1.y = acc[mf][nf][3] + bb.y;
                *(float2*)&Cout[(size_t)m0 * Nc + col] = v0;
                *(float2*)&Cout[(size_t)(m0 + 8) * Nc + col] = v1;
            }
        }
    } else {
        // ---- fused LayerNorm + fp16 epilogue ----
        float* S = (float*)smh0;
#pragma unroll
        for (int mf = 0; mf < 4; mf++) {
#pragma unroll
            for (int nf = 0; nf < 4; nf++) {
                int ml = wm * 64 + mf * 16 + (lane >> 2);
                int cl = wn * 32 + nf * 8 + (lane & 3) * 2;
                float2 bb = *(const float2*)&bias[bn + cl];
                float2 v0, v1;
                v0.x = acc[mf][nf][0] + bb.x;
                v0.y = acc[mf][nf][1] + bb.y;
                v1.x = acc[mf][nf][2] + bb.x;
                v1.y = acc[mf][nf][3] + bb.y;
                *(float2*)&S[ml * LN_SS + cl] = v0;
                *(float2*)&S[(ml + 8) * LN_SS + cl] = v1;
            }
        }
        __syncthreads();

        const int row = tid & 127;
        const int hb = tid >> 7;
        const int gc = bn + hb * 64;
        const int part = gc >> 10;             // 0=q 1=k 2=v
        const int hh = (gc >> 6) & (HEADS - 1);
        const int m = bm + row;
        const float* Sr = &S[row * LN_SS + hb * 64];

        float sum = 0.f, sq = 0.f;
#pragma unroll
        for (int j = 0; j < 32; j++) {
            float2 t = *(const float2*)&Sr[j * 2];
            sum += t.x + t.y;
            sq += t.x * t.x + t.y * t.y;
        }
        float mu = 0.f, rstd = 1.f;
        const float* gp = (part == 0) ? qg : kg;
        const float* bp = (part == 0) ? qb : kb;
        if (part < 2) {
            mu = sum * (1.f / 64.f);
            float var = sq * (1.f / 64.f) - mu * mu;
            rstd = rsqrtf(var + 1e-6f);
        }
        __half* dst = (part == 0) ? g_q16 : (part == 1) ? g_k16 : g_v16;
        size_t obase = ((size_t)hh * NTOK + m) * HD;

#pragma unroll
        for (int jj = 0; jj < 8; jj++) {
            float v[8];
#pragma unroll
            for (int k = 0; k < 4; k++) {
                float2 t = *(const float2*)&Sr[jj * 8 + k * 2];
                v[k * 2] = t.x;
                v[k * 2 + 1] = t.y;
            }
            if (part < 2) {
#pragma unroll
                for (int k = 0; k < 8; k++)
                    v[k] = (v[k] - mu) * rstd * gp[jj * 8 + k] + bp[jj * 8 + k];
            }
            uint32_t w[4];
#pragma unroll
            for (int k = 0; k < 4; k++)
                w[k] = pack_h16(v[2 * k], v[2 * k + 1]);
            *(uint4*)&dst[obase + jj * 8] = *(uint4*)w;
        }
    }
}

// ---------------------------------------------------------------------------
// fp16 HMMA flash attention (attn10): attn9 + live-tile skipping.
// Per (s,split): nt = ceil(clamp(nreal[s]-split*992, 0, 992)/32) tiles.
// Padded tail tiles contribute exactly 0 -> skipping is bit-exact.
// ---------------------------------------------------------------------------
#define AST 72
#define KARR (KT * AST)
#define BIAS_OFF (2 * KARR)
#define AT_SMEM_BYTES (BIAS_OFF * 2 + KT * 4 + 16)

__global__ void __launch_bounds__(224, 2)
attn10_kernel()
{
    extern __shared__ __half smh[];
    __half* Tile = smh;
    float* Bs = (float*)(smh + BIAS_OFF);
    const uint32_t su = smem_u32(smh);

    const int s = blockIdx.x, h = blockIdx.y, split = blockIdx.z;
    const int tid = threadIdx.x, wid = tid >> 5, lane = tid & 31;
    const int m0 = wid * 32;

    // live tile count for this (s, split)
    int keys_here = g_nreal[s] - split * KVSPL;
    keys_here = keys_here < 0 ? 0 : (keys_here > KVSPL ? KVSPL : keys_here);
    const int nt = (keys_here + KT - 1) / KT;

    const __half* q16 = g_q16 + ((size_t)h * NTOK + (size_t)s * PTOK) * HD;
    const __half* k16 = g_k16 + (size_t)h * NTOK * HD;
    const __half* v16 = g_v16 + (size_t)h * NTOK * HD;

    float o[2][8][4];
    float lsum[2][2];
#pragma unroll
    for (int mf = 0; mf < 2; mf++) {
        lsum[mf][0] = 0.f; lsum[mf][1] = 0.f;
#pragma unroll
        for (int nf = 0; nf < 8; nf++)
#pragma unroll
            for (int e = 0; e < 4; e++) o[mf][nf][e] = 0.f;
    }

    if (nt > 0) {
        uint32_t qf[2][4][4];
        {
            int r = lane >> 2, c2 = (lane & 3) * 2;
#pragma unroll
            for (int mf = 0; mf < 2; mf++) {
                int r0 = m0 + mf * 16 + r;
                int r1 = r0 + 8;
                if (r0 > PTOK - 1) r0 = PTOK - 1;
                if (r1 > PTOK - 1) r1 = PTOK - 1;
#pragma unroll
                for (int kf = 0; kf < 4; kf++) {
                    int c0 = kf * 16 + c2;
                    qf[mf][kf][0] = *(const uint32_t*)(q16 + (size_t)r0 * HD + c0);
                    qf[mf][kf][1] = *(const uint32_t*)(q16 + (size_t)r1 * HD + c0);
                    qf[mf][kf][2] = *(const uint32_t*)(q16 + (size_t)r0 * HD + c0 + 8);
                    qf[mf][kf][3] = *(const uint32_t*)(q16 + (size_t)r1 * HD + c0 + 8);
                }
            }
        }

        const int pbase = s * MKPAD + split * KVSPL;

        const uint32_t kaddr = su + 2 * (
            ((lane & 7) + ((lane >> 4) & 1) * 8) * AST + ((lane >> 3) & 1) * 8);
        const uint32_t vaddr = su + 2 * (KARR
            + ((lane & 7) + ((lane >> 3) & 1) * 8) * AST + ((lane >> 4) & 1) * 8);

        uint4 pf[3];
        float pbias = 0.f;
#pragma unroll
        for (int it = 0; it < 3; it++) {
            int slot = tid + it * 224;
            if (slot < 512) {
                int a = slot >> 8, r = (slot >> 3) & 31, seg = slot & 7;
                int tok = g_gidx2[pbase + r];
                const __half* bp = (a == 0) ? k16 : v16;
                pf[it] = *(const uint4*)(bp + (size_t)tok * HD + seg * 8);
            }
        }
        if (tid < KT) pbias = g_bias2[pbase + tid];

        for (int t = 0; t < nt; t++) {
            __syncthreads();
#pragma unroll
            for (int it = 0; it < 3; it++) {
                int slot = tid + it * 224;
                if (slot < 512) {
                    int a = slot >> 8, r = (slot >> 3) & 31, seg = slot & 7;
                    *(uint4*)&Tile[a * KARR + r * AST + seg * 8] = pf[it];
                }
            }
            if (tid < KT) Bs[tid] = pbias;
            __syncthreads();

            if (t + 1 < nt) {
                int ib = pbase + (t + 1) * KT;
#pragma unroll
                for (int it = 0; it < 3; it++) {
                    int slot = tid + it * 224;
                    if (slot < 512) {
                        int a = slot >> 8, r = (slot >> 3) & 31, seg = slot & 7;
                        int tok = g_gidx2[ib + r];
                        const __half* bp = (a == 0) ? k16 : v16;
                        pf[it] = *(const uint4*)(bp + (size_t)tok * HD + seg * 8);
                    }
                }
                if (tid < KT) pbias = g_bias2[ib + tid];
            }

            // ---- QK: fp16 single product ----
            float sc[2][4][4];
#pragma unroll
            for (int mf = 0; mf < 2; mf++)
#pragma unroll
                for (int nf = 0; nf < 4; nf++)
#pragma unroll
                    for (int e = 0; e < 4; e++) sc[mf][nf][e] = 0.f;

#pragma unroll
            for (int kf = 0; kf < 4; kf++) {
                uint32_t bh0[4], bh1[4];
                ldsm4(kaddr + kf * 32, bh0[0], bh0[1], bh0[2], bh0[3]);
                ldsm4(kaddr + kf * 32 + 16 * AST * 2, bh1[0], bh1[1], bh1[2], bh1[3]);
#pragma unroll
                for (int mf = 0; mf < 2; mf++) {
                    uint32_t q0 = qf[mf][kf][0], q1 = qf[mf][kf][1];
                    uint32_t q2 = qf[mf][kf][2], q3 = qf[mf][kf][3];
                    mma_f16(sc[mf][0][0], sc[mf][0][1], sc[mf][0][2], sc[mf][0][3],
                            q0, q1, q2, q3, bh0[0], bh0[1]);
                    mma_f16(sc[mf][1][0], sc[mf][1][1], sc[mf][1][2], sc[mf][1][3],
                            q0, q1, q2, q3, bh0[2], bh0[3]);
                    mma_f16(sc[mf][2][0], sc[mf][2][1], sc[mf][2][2], sc[mf][2][3],
                            q0, q1, q2, q3, bh1[0], bh1[1]);
                    mma_f16(sc[mf][3][0], sc[mf][3][1], sc[mf][3][2], sc[mf][3][3],
                            q0, q1, q2, q3, bh1[2], bh1[3]);
                }
            }

            // ---- softmax weights, packed to fp16 ----
            uint32_t phi[2][2][4];
#pragma unroll
            for (int mf = 0; mf < 2; mf++) {
#pragma unroll
                for (int nf = 0; nf < 4; nf++) {
                    float2 bb = *(const float2*)&Bs[nf * 8 + (lane & 3) * 2];
                    float p0 = __expf(fmaf(sc[mf][nf][0], 0.125f, bb.x));
                    float p1 = __expf(fmaf(sc[mf][nf][1], 0.125f, bb.y));
                    float p2 = __expf(fmaf(sc[mf][nf][2], 0.125f, bb.x));
                    float p3 = __expf(fmaf(sc[mf][nf][3], 0.125f, bb.y));
                    lsum[mf][0] += p0 + p1;
                    lsum[mf][1] += p2 + p3;
                    int kf2 = nf >> 1, hf = (nf & 1) * 2;
                    phi[mf][kf2][hf] = pack_h16(p0, p1);
                    phi[mf][kf2][hf + 1] = pack_h16(p2, p3);
                }
            }

            // ---- PV: fp16 single product, V via ldsm.trans ----
#pragma unroll
            for (int kf = 0; kf < 2; kf++) {
                uint32_t vhf[16];
#pragma unroll
                for (int db = 0; db < 4; db++) {
                    ldsm4t(vaddr + kf * (16 * AST * 2) + db * 32,
                           vhf[db * 4], vhf[db * 4 + 1], vhf[db * 4 + 2], vhf[db * 4 + 3]);
                }
#pragma unroll
                for (int mf = 0; mf < 2; mf++) {
#pragma unroll
                    for (int nfd = 0; nfd < 8; nfd++) {
                        int vi = (nfd >> 1) * 4 + (nfd & 1) * 2;
                        mma_f16(o[mf][nfd][0], o[mf][nfd][1], o[mf][nfd][2], o[mf][nfd][3],
                                phi[mf][kf][0], phi[mf][kf][1], phi[mf][kf][2], phi[mf][kf][3],
                                vhf[vi], vhf[vi + 1]);
                    }
                }
            }
        }

        // reduce l over the 4 lanes sharing each row
#pragma unroll
        for (int mf = 0; mf < 2; mf++) {
#pragma unroll
            for (int j = 0; j < 2; j++) {
                float v = lsum[mf][j];
                v += __shfl_xor_sync(0xffffffffu, v, 1);
                v += __shfl_xor_sync(0xffffffffu, v, 2);
                lsum[mf][j] = v;
            }
        }
    }

    // epilogue: store UNNORMALIZED partials (fp32) + row sums (zeros if nt==0)
    {
        int r = lane >> 2, c2 = (lane & 3) * 2;
        const size_t rrbase = ((size_t)(split * SFR + s) * HEADS + h) * PTOK;
#pragma unroll
        for (int mf = 0; mf < 2; mf++) {
            int rowq0 = m0 + mf * 16 + r;
            int rowq1 = rowq0 + 8;
            if (rowq0 < PTOK) {
                float* dst = g_pacc + (rrbase + rowq0) * HD + c2;
#pragma unroll
                for (int nfd = 0; nfd < 8; nfd++) {
                    float2 v; v.x = o[mf][nfd][0]; v.y = o[mf][nfd][1];
                    *(float2*)(dst + nfd * 8) = v;
                }
                if ((lane & 3) == 0) g_pl[rrbase + rowq0] = lsum[mf][0];
            }
            if (rowq1 < PTOK) {
                float* dst = g_pacc + (rrbase + rowq1) * HD + c2;
#pragma unroll
                for (int nfd = 0; nfd < 8; nfd++) {
                    float2 v; v.x = o[mf][nfd][2]; v.y = o[mf][nfd][3];
                    *(float2*)(dst + nfd * 8) = v;
                }
                if ((lane & 3) == 0) g_pl[rrbase + rowq1] = lsum[mf][1];
            }
        }
    }
}

// ---------------------------------------------------------------------------
// Combine split partials: (n0+n1)/(l0+l1) -> fp16 token-major plane g_a16.
// ---------------------------------------------------------------------------
__global__ void __launch_bounds__(256)
combine_kernel()
{
    int idx = blockIdx.x * blockDim.x + threadIdx.x;
    const int total = SFR * HEADS * PTOK * (HD / 4);
    if (idx >= total) return;
    int c4 = idx & 15;
    int shp = idx >> 4;
    size_t row0 = shp;
    size_t row1 = (size_t)SFR * HEADS * PTOK + shp;
    float4 a = ((const float4*)(g_pacc + row0 * HD))[c4];
    float4 b = ((const float4*)(g_pacc + row1 * HD))[c4];
    float inv = 1.f / (g_pl[row0] + g_pl[row1]);
    float f0 = (a.x + b.x) * inv;
    float f1 = (a.y + b.y) * inv;
    float f2 = (a.z + b.z) * inv;
    float f3 = (a.w + b.w) * inv;
    int p = shp % PTOK;
    int sh = shp / PTOK;
    int hh = sh % HEADS;
    int ss = sh / HEADS;
    size_t base = (size_t)(ss * PTOK + p) * CDIM + hh * HD + c4 * 4;
    uint2 w;
    w.x = pack_h16(f0, f1);
    w.y = pack_h16(f2, f3);
    *(uint2*)&g_a16[base] = w;
}

// ---------------------------------------------------------------------------
extern "C" void kernel_launch(void* const* d_in, const int* in_sizes, int n_in,
                              void* d_out, int out_size)
{
    const float* x     = (const float*)d_in[0];
    const float* Wqkv  = (const float*)d_in[1];
    const float* bqkv  = (const float*)d_in[2];
    const float* qg    = (const float*)d_in[3];
    const float* qb    = (const float*)d_in[4];
    const float* kg    = (const float*)d_in[5];
    const float* kb    = (const float*)d_in[6];
    const float* Wproj = (const float*)d_in[7];
    const float* bproj = (const float*)d_in[8];
    const int*   gidx  = (const int*)d_in[9];
    const float* abias = (const float*)d_in[10];
    float* out = (float*)d_out;

    static int attr_set = 0;
    if (!attr_set) {
        cudaFuncSetAttribute(hmma_gemm_kernel<0>,
                             cudaFuncAttributeMaxDynamicSharedMemorySize, GEMM_SMEM0);
        cudaFuncSetAttribute(hmma_gemm_kernel<1>,
                             cudaFuncAttributeMaxDynamicSharedMemorySize, GEMM_SMEM1);
        cudaFuncSetAttribute(attn10_kernel,
                             cudaFuncAttributeMaxDynamicSharedMemorySize, AT_SMEM_BYTES);
        attr_set = 1;
    }

    const int n4 = NTOK * KDIM / 4;

    // 0) prep
    split_kernel<<<n4 / 256, 256>>>(x, n4);
    pad_kernel<<<(SFR * MKPAD + 255) / 256, 256>>>(gidx, abias);
    count_kernel<<<SFR, 256>>>(abias);
    wsplit_kernel<0><<<dim3(NQKV / 32, KDIM / 32), 256>>>(Wqkv, NQKV);
    wsplit_kernel<1><<<dim3(1024 / 32, KDIM / 32), 256>>>(Wproj, 1024);

    // 1) QKV GEMM (fp16) with FUSED LayerNorm + fp16 epilogue -> g_{q,k,v}16
    hmma_gemm_kernel<0><<<dim3(NQKV / 128, NTOK / 128), 256, GEMM_SMEM0>>>(
        bqkv, nullptr, NQKV, qg, qb, kg, kb);

    // 2) fp16 flash attention, KV-split x2, live-tile skipping -> fp32 partials
    attn10_kernel<<<dim3(SFR, HEADS, NSPL), 224, AT_SMEM_BYTES>>>();

    // 2b) combine partials -> g_a16
    {
        const int total = SFR * HEADS * PTOK * (HD / 4);
        combine_kernel<<<(total + 255) / 256, 256>>>();
    }

    // 3) proj GEMM (fp16) -> d_out
    hmma_gemm_kernel<1><<<dim3(1024 / 128, NTOK / 128), 256, GEMM_SMEM1>>>(
        bproj, out, 1024, nullptr, nullptr, nullptr, nullptr);
}